// round 4
// baseline (speedup 1.0000x reference)
#include <cuda_runtime.h>
#include <cuda_bf16.h>

#define M_PTS   200000
#define N_CAM   6
#define C_IMG   96
#define H_FEAT  32
#define W_FEAT  88
#define PTS_DIM 128
#define KIN     224           // 128 + 96
#define GZ      32
#define GY      512
#define GX      448
#define GRID_N  (GZ*GY*GX)    // 7,340,032

#define NTAP_O   26           // non-self taps
#define PAIR_CAP 200000
#define NT_SELF  1563         // ceil(200000/128)
#define NCHUNK   28           // 224/8

// block-range dispatch for merged kernels
#define TRANS_TOT  (N_CAM*H_FEAT*W_FEAT*C_IMG)     // 1,622,016
#define NB_TRANS   ((TRANS_TOT + 255)/256)         // 6336
#define NB_GRID    (GRID_N/4/256)                  // 7168
#define NB_SETUP   1
#define NB_MEGA1   (NB_TRANS + NB_GRID + NB_SETUP)

#define NB_SAMPLE  (M_PTS/8)                       // 25000
#define NB_BPAIR   ((M_PTS + 255)/256)             // 782
#define NB_ZACC    ((M_PTS*PTS_DIM/4 + 255)/256)   // 25000
#define NB_MEGA2   (NB_SAMPLE + NB_BPAIR + NB_ZACC)

typedef unsigned long long u64;

// packed f32x2 FMA: d = a*b + d  (two independent fp32 lanes, .rn each)
#define FMA2(d,a,b) asm("fma.rn.f32x2 %0, %1, %2, %0;" : "+l"(d) : "l"(a), "l"(b))
#define PACK2(d,x)  asm("mov.b64 %0, {%1, %1};" : "=l"(d) : "f"(x))
#define UNPACK2(lo,hi,v) asm("mov.b64 {%0, %1}, %2;" : "=f"(lo), "=f"(hi) : "l"(v))

// ---------------- device globals (scratch; no cudaMalloc allowed) ----------------
__device__ float g_imgT[N_CAM*H_FEAT*W_FEAT*C_IMG];   // NHWC transposed image feats
__device__ int   g_grid[GRID_N];
__device__ float g_sampled[(size_t)M_PTS*C_IMG];
__device__ float g_acc[(size_t)M_PTS*PTS_DIM];
__device__ int2  g_pairs[(size_t)NTAP_O*PAIR_CAP];    // (out_idx, nid) per tap
__device__ int   g_np[NTAP_O];
__device__ float g_cam[N_CAM*24];
__device__ float g_bnscale[PTS_DIM];
__device__ float g_bnbias[PTS_DIM];

// ================= mega kernel 1: transpose + grid init + setup =================
__global__ void mega_setup_kernel(const float* __restrict__ img,
                                  const float* __restrict__ l2i,
                                  const float* __restrict__ iaug,
                                  const float* __restrict__ laug,
                                  const float* __restrict__ gamma,
                                  const float* __restrict__ beta,
                                  const float* __restrict__ mean,
                                  const float* __restrict__ var) {
    int b = blockIdx.x;
    if (b < NB_TRANS) {
        int o = b * 256 + threadIdx.x;
        if (o < TRANS_TOT) {
            int c = o % C_IMG; int rest = o / C_IMG;
            int x = rest % W_FEAT; rest /= W_FEAT;
            int y = rest % H_FEAT; int n = rest / H_FEAT;
            g_imgT[o] = img[(((size_t)n*C_IMG + c)*H_FEAT + y)*W_FEAT + x];
        }
        return;
    }
    b -= NB_TRANS;
    if (b < NB_GRID) {
        int idx = b * 256 + threadIdx.x;
        ((int4*)g_grid)[idx] = make_int4(-1,-1,-1,-1);
        return;
    }
    // setup block
    int t = threadIdx.x;
    if (t < PTS_DIM) {
        float s = rsqrtf(var[t] + 1e-5f) * gamma[t];
        g_bnscale[t] = s;
        g_bnbias[t]  = beta[t] - mean[t] * s;
    }
    if (t >= 128 && t < 128 + NTAP_O) g_np[t-128] = 0;
    if (t == 0) {
        float a0=laug[0],a1=laug[1],a2=laug[2];
        float a3=laug[4],a4=laug[5],a5=laug[6];
        float a6=laug[8],a7=laug[9],a8=laug[10];
        float tx=laug[3], ty=laug[7], tz=laug[11];
        float det = a0*(a4*a8-a5*a7) - a1*(a3*a8-a5*a6) + a2*(a3*a7-a4*a6);
        float id = 1.0f/det;
        float inv[9] = {
            (a4*a8-a5*a7)*id, (a2*a7-a1*a8)*id, (a1*a5-a2*a4)*id,
            (a5*a6-a3*a8)*id, (a0*a8-a2*a6)*id, (a2*a3-a0*a5)*id,
            (a3*a7-a4*a6)*id, (a1*a6-a0*a7)*id, (a0*a4-a1*a3)*id };
        for (int n = 0; n < N_CAM; n++) {
            const float* L = l2i + n*16;
            float P[9], q[3];
            for (int r = 0; r < 3; r++) {
                for (int c = 0; c < 3; c++)
                    P[r*3+c] = L[r*4+0]*inv[0*3+c] + L[r*4+1]*inv[1*3+c] + L[r*4+2]*inv[2*3+c];
                q[r] = L[r*4+3] - (P[r*3+0]*tx + P[r*3+1]*ty + P[r*3+2]*tz);
            }
            float* gc = g_cam + n*24;
            for (int r = 0; r < 3; r++) {
                gc[r*4+0]=P[r*3+0]; gc[r*4+1]=P[r*3+1]; gc[r*4+2]=P[r*3+2]; gc[r*4+3]=q[r];
            }
            const float* A = iaug + n*16;
            for (int r = 0; r < 2; r++) {
                gc[12+r*4+0]=A[r*4+0]; gc[12+r*4+1]=A[r*4+1]; gc[12+r*4+2]=A[r*4+2]; gc[12+r*4+3]=A[r*4+3];
            }
        }
    }
}

// ================= scatter (needs full grid init) =================
__global__ void scatter_kernel(const int* __restrict__ vc) {
    int i = blockIdx.x * 256 + threadIdx.x;
    if (i >= M_PTS) return;
    int4 c4 = ((const int4*)vc)[i];
    int cell = (c4.y*GY + c4.z)*GX + c4.w;
    atomicMax(&g_grid[cell], i);     // last-write-wins (highest index) for duplicates
}

// ================= mega kernel 2: sample + build_pairs + zero_acc =================
__device__ __forceinline__ void sample_body(const int* __restrict__ vc, int blk) {
    int warp = blk * 8 + (threadIdx.x >> 5);
    int lane = threadIdx.x & 31;
    if (warp >= M_PTS) return;
    int4 c4 = ((const int4*)vc)[warp];
    float px = (float)c4.w, py = (float)c4.z, pz = (float)c4.y;
    float4 acc = make_float4(0.f,0.f,0.f,0.f);

    #pragma unroll 1
    for (int n = 0; n < N_CAM; n++) {
        const float* cam = g_cam + n*24;
        float X = cam[0]*px + cam[1]*py + cam[2]*pz  + cam[3];
        float Y = cam[4]*px + cam[5]*py + cam[6]*pz  + cam[7];
        float Z = cam[8]*px + cam[9]*py + cam[10]*pz + cam[11];
        float z = fminf(fmaxf(Z, 1e-5f), 100000.0f);
        float rz = 1.0f / z;
        float vx = X*rz, vy = Y*rz;
        float u = cam[12]*vx + cam[13]*vy + cam[14]*z + cam[15];
        float v = cam[16]*vx + cam[17]*vy + cam[18]*z + cam[19];
        float xf = u * (87.0f/704.0f);
        float yf = v * (31.0f/256.0f);
        float x0 = floorf(xf), y0 = floorf(yf);
        float wx1 = xf - x0, wy1 = yf - y0;
        float wx0 = 1.0f - wx1, wy0 = 1.0f - wy1;

        float cx[4] = {x0, x0+1.0f, x0,      x0+1.0f};
        float cy[4] = {y0, y0,      y0+1.0f, y0+1.0f};
        float cw[4] = {wx0*wy0, wx1*wy0, wx0*wy1, wx1*wy1};
        #pragma unroll
        for (int q = 0; q < 4; q++) {
            if (cx[q] >= 0.0f && cx[q] <= 87.0f && cy[q] >= 0.0f && cy[q] <= 31.0f && lane < 24) {
                const float4* base = (const float4*)(g_imgT +
                    (((size_t)n*H_FEAT + (int)cy[q])*W_FEAT + (int)cx[q]) * C_IMG);
                float4 f = __ldg(base + lane);
                float w = cw[q];
                acc.x += w*f.x; acc.y += w*f.y; acc.z += w*f.z; acc.w += w*f.w;
            }
        }
    }
    if (lane < 24)
        ((float4*)(g_sampled + (size_t)warp*C_IMG))[lane] = acc;
}

__device__ __forceinline__ void build_pairs_body(const int* __restrict__ vc, int blk) {
    int tid = threadIdx.x;
    int i = blk * 256 + tid;
    int lane = tid & 31;
    bool live = i < M_PTS;
    int4 c4 = live ? ((const int4*)vc)[i] : make_int4(0,0,0,0);

    __shared__ int s_cnt[NTAP_O];
    __shared__ int s_gbase[NTAP_O];
    if (tid < NTAP_O) s_cnt[tid] = 0;
    __syncthreads();

    int nids[NTAP_O];
    int idxs[NTAP_O];
    unsigned vm = 0;

    #pragma unroll
    for (int t = 0; t < NTAP_O; t++) {
        int k = (t < 13) ? t : t + 1;
        int dz = k/9 - 1, dy = (k/3)%3 - 1, dx = k%3 - 1;
        int nz = c4.y + dz, ny = c4.z + dy, nx = c4.w + dx;
        bool valid = live && nz >= 0 && nz < GZ && ny >= 0 && ny < GY && nx >= 0 && nx < GX;
        int nid = -1;
        if (valid) nid = __ldg(&g_grid[(nz*GY + ny)*GX + nx]);
        valid = valid && (nid >= 0);
        unsigned m = __ballot_sync(0xffffffffu, valid);
        if (m != 0) {
            int ldr = __ffs(m) - 1;
            int wb = 0;
            if (lane == ldr) wb = atomicAdd(&s_cnt[t], __popc(m));
            wb = __shfl_sync(0xffffffffu, wb, ldr);
            if (valid) {
                int rank = __popc(m & ((1u << lane) - 1u));
                nids[t] = nid;
                idxs[t] = wb + rank;
                vm |= (1u << t);
            }
        }
    }
    __syncthreads();
    if (tid < NTAP_O) s_gbase[tid] = atomicAdd(&g_np[tid], s_cnt[tid]);
    __syncthreads();
    #pragma unroll
    for (int t = 0; t < NTAP_O; t++) {
        if ((vm >> t) & 1u)
            g_pairs[(size_t)t*PAIR_CAP + s_gbase[t] + idxs[t]] = make_int2(i, nids[t]);
    }
}

__global__ void mega_mid_kernel(const int* __restrict__ vc) {
    int b = blockIdx.x;
    if (b < NB_SAMPLE) { sample_body(vc, b); return; }
    b -= NB_SAMPLE;
    if (b < NB_BPAIR)  { build_pairs_body(vc, b); return; }
    b -= NB_BPAIR;
    {
        int idx = b * 256 + threadIdx.x;
        if (idx < (M_PTS*PTS_DIM)/4) ((float4*)g_acc)[idx] = make_float4(0.f,0.f,0.f,0.f);
    }
}

// ---------------- sparse conv as 128x128xK224 register-tiled SGEMM (f32x2 packed) ------
template<bool SELF>
__global__ void __launch_bounds__(256, 2)
conv_gemm_kernel(const float* __restrict__ pts,
                 const int*   __restrict__ vc,
                 const float* __restrict__ convw,
                 float*       __restrict__ out) {
    __shared__ float s_a[2][8][128];
    __shared__ float s_b[2][8][128];
    __shared__ int s_out[128];
    __shared__ int s_nid[128];

    int tid = threadIdx.x;
    int k, np, tile0, tstep;
    if (SELF) { k = 13; np = M_PTS; tile0 = blockIdx.x; tstep = NT_SELF; }
    else {
        int t = blockIdx.y;
        k = (t < 13) ? t : t + 1;
        np = g_np[t];
        tile0 = blockIdx.x; tstep = 64;
    }
    const float* wk = convw + (size_t)k*KIN*PTS_DIM;
    const int tpair = SELF ? 0 : (int)blockIdx.y;

    int ty = tid >> 4, tx = tid & 15;       // 16x16 thread grid
    int myrow = tid >> 1, half = tid & 1;   // for A gather: 2 threads/row

    for (int tile = tile0; tile*128 < np; tile += tstep) {
        __syncthreads();   // protect s_out/s_nid from previous tile epilogue
        int base = tile*128;
        if (tid < 128) {
            int r = base + tid;
            int o = -1, nid = 0;
            if (r < np) {
                if (SELF) {
                    int4 c4 = ((const int4*)vc)[r];
                    o = r;
                    nid = __ldg(&g_grid[(c4.y*GY + c4.z)*GX + c4.w]);
                } else {
                    int2 pr = g_pairs[(size_t)tpair*PAIR_CAP + r];
                    o = pr.x; nid = pr.y;
                }
            }
            s_out[tid] = o;
            s_nid[tid] = nid;
        }
        __syncthreads();

        int nid = s_nid[myrow];
        const float* arow_p = pts       + (size_t)nid*PTS_DIM + half*4;
        const float* arow_s = g_sampled + (size_t)nid*C_IMG  + half*4;

        u64 acc2[8][4];     // [p][q-pair], 2 output channels per entry
        #pragma unroll
        for (int p = 0; p < 8; p++)
            #pragma unroll
            for (int q = 0; q < 4; q++) acc2[p][q] = 0ull;

        // preload chunk 0
        float4 av = *(const float4*)(arow_p);
        float4 bv = *(const float4*)(wk + tid*4);
        {
            s_a[0][half*4+0][myrow] = av.x;
            s_a[0][half*4+1][myrow] = av.y;
            s_a[0][half*4+2][myrow] = av.z;
            s_a[0][half*4+3][myrow] = av.w;
            ((float4*)&s_b[0][0][0])[tid] = bv;
        }
        __syncthreads();

        int buf = 0;
        #pragma unroll 1
        for (int c = 0; c < NCHUNK; c++) {
            if (c + 1 < NCHUNK) {
                int kc0 = (c+1)*8;
                const float* ap = (kc0 < PTS_DIM) ? (arow_p + kc0) : (arow_s + (kc0 - PTS_DIM));
                av = *(const float4*)ap;
                bv = *(const float4*)(wk + kc0*PTS_DIM + tid*4);
            }
            #pragma unroll
            for (int kc = 0; kc < 8; kc++) {
                float4 a0 = *(float4*)&s_a[buf][kc][ty*8];
                float4 a1 = *(float4*)&s_a[buf][kc][ty*8+4];
                ulonglong2 bq0 = *(ulonglong2*)&s_b[buf][kc][tx*8];
                ulonglong2 bq1 = *(ulonglong2*)&s_b[buf][kc][tx*8+4];
                u64 b2[4] = {bq0.x, bq0.y, bq1.x, bq1.y};
                float ar[8] = {a0.x,a0.y,a0.z,a0.w,a1.x,a1.y,a1.z,a1.w};
                #pragma unroll
                for (int p = 0; p < 8; p++) {
                    u64 ad;
                    PACK2(ad, ar[p]);
                    FMA2(acc2[p][0], ad, b2[0]);
                    FMA2(acc2[p][1], ad, b2[1]);
                    FMA2(acc2[p][2], ad, b2[2]);
                    FMA2(acc2[p][3], ad, b2[3]);
                }
            }
            if (c + 1 < NCHUNK) {
                int nb = buf ^ 1;
                s_a[nb][half*4+0][myrow] = av.x;
                s_a[nb][half*4+1][myrow] = av.y;
                s_a[nb][half*4+2][myrow] = av.z;
                s_a[nb][half*4+3][myrow] = av.w;
                ((float4*)&s_b[nb][0][0])[tid] = bv;
            }
            __syncthreads();
            buf ^= 1;
        }

        // unpack accumulators
        float acc[8][8];
        #pragma unroll
        for (int p = 0; p < 8; p++)
            #pragma unroll
            for (int q = 0; q < 4; q++)
                UNPACK2(acc[p][2*q], acc[p][2*q+1], acc2[p][q]);

        // epilogue
        if (SELF) {
            float sc[8], bi[8];
            #pragma unroll
            for (int q = 0; q < 8; q++) {
                sc[q] = g_bnscale[tx*8+q];
                bi[q] = g_bnbias[tx*8+q];
            }
            #pragma unroll
            for (int p = 0; p < 8; p++) {
                int o = s_out[ty*8+p];
                if (o >= 0) {
                    const float4* gp = (const float4*)(g_acc + (size_t)o*PTS_DIM + tx*8);
                    float4 g0 = gp[0], g1 = gp[1];
                    float4 r0, r1;
                    r0.x = fmaxf((acc[p][0]+g0.x)*sc[0]+bi[0], 0.f);
                    r0.y = fmaxf((acc[p][1]+g0.y)*sc[1]+bi[1], 0.f);
                    r0.z = fmaxf((acc[p][2]+g0.z)*sc[2]+bi[2], 0.f);
                    r0.w = fmaxf((acc[p][3]+g0.w)*sc[3]+bi[3], 0.f);
                    r1.x = fmaxf((acc[p][4]+g1.x)*sc[4]+bi[4], 0.f);
                    r1.y = fmaxf((acc[p][5]+g1.y)*sc[5]+bi[5], 0.f);
                    r1.z = fmaxf((acc[p][6]+g1.z)*sc[6]+bi[6], 0.f);
                    r1.w = fmaxf((acc[p][7]+g1.w)*sc[7]+bi[7], 0.f);
                    float4* op = (float4*)(out + (size_t)o*PTS_DIM + tx*8);
                    op[0] = r0; op[1] = r1;
                }
            }
        } else {
            #pragma unroll
            for (int p = 0; p < 8; p++) {
                int o = s_out[ty*8+p];
                if (o >= 0) {
                    float* gp = g_acc + (size_t)o*PTS_DIM + tx*8;
                    #pragma unroll
                    for (int q = 0; q < 8; q++)
                        atomicAdd(gp + q, acc[p][q]);
                }
            }
        }
    }
}

// ---------------- launch ----------------
extern "C" void kernel_launch(void* const* d_in, const int* in_sizes, int n_in,
                              void* d_out, int out_size) {
    const float* pts   = (const float*)d_in[0];
    const int*   vc    = (const int*)  d_in[1];
    const float* img   = (const float*)d_in[2];
    const float* l2i   = (const float*)d_in[3];
    const float* iaug  = (const float*)d_in[4];
    const float* laug  = (const float*)d_in[5];
    const float* convw = (const float*)d_in[6];
    const float* gamma = (const float*)d_in[7];
    const float* beta  = (const float*)d_in[8];
    const float* mean  = (const float*)d_in[9];
    const float* var   = (const float*)d_in[10];
    float* out = (float*)d_out;

    mega_setup_kernel<<<NB_MEGA1, 256>>>(img, l2i, iaug, laug, gamma, beta, mean, var);
    scatter_kernel<<<(M_PTS + 255)/256, 256>>>(vc);
    mega_mid_kernel<<<NB_MEGA2, 256>>>(vc);
    conv_gemm_kernel<false><<<dim3(64, NTAP_O), 256>>>(pts, vc, convw, out);
    conv_gemm_kernel<true ><<<NT_SELF, 256>>>(pts, vc, convw, out);
}

// round 5
// speedup vs baseline: 1.1295x; 1.1295x over previous
#include <cuda_runtime.h>
#include <cuda_bf16.h>

#define M_PTS   200000
#define N_CAM   6
#define C_IMG   96
#define H_FEAT  32
#define W_FEAT  88
#define PTS_DIM 128
#define KIN     224           // 128 + 96
#define GZ      32
#define GY      512
#define GX      448
#define GRID_N  (GZ*GY*GX)    // 7,340,032

#define NTAP_O   26           // non-self taps
#define PAIR_CAP 200000
#define NT_SELF  1563         // ceil(200000/128)
#define NCHUNK   14           // 224/16

// block-range dispatch for merged kernels
#define TRANS_TOT  (N_CAM*H_FEAT*W_FEAT*C_IMG)     // 1,622,016
#define NB_TRANS   ((TRANS_TOT + 255)/256)         // 6336
#define NB_GRID    (GRID_N/4/256)                  // 7168
#define NB_SETUP   1
#define NB_MEGA1   (NB_TRANS + NB_GRID + NB_SETUP)

#define NB_SAMPLE  (M_PTS/8)                       // 25000
#define NB_BPAIR   ((M_PTS + 255)/256)             // 782
#define NB_ZACC    ((M_PTS*PTS_DIM/4 + 255)/256)   // 25000
#define NB_MEGA2   (NB_SAMPLE + NB_BPAIR + NB_ZACC)

typedef unsigned long long u64;

// packed f32x2 FMA: d = a*b + d  (two independent fp32 lanes, .rn each)
#define FMA2(d,a,b) asm("fma.rn.f32x2 %0, %1, %2, %0;" : "+l"(d) : "l"(a), "l"(b))
#define PACK2(d,x)  asm("mov.b64 %0, {%1, %1};" : "=l"(d) : "f"(x))
#define UNPACK2(lo,hi,v) asm("mov.b64 {%0, %1}, %2;" : "=f"(lo), "=f"(hi) : "l"(v))

// ---------------- device globals (scratch; no cudaMalloc allowed) ----------------
__device__ float g_imgT[N_CAM*H_FEAT*W_FEAT*C_IMG];   // NHWC transposed image feats
__device__ int   g_grid[GRID_N];
__device__ float g_sampled[(size_t)M_PTS*C_IMG];
__device__ float g_acc[(size_t)M_PTS*PTS_DIM];
__device__ int2  g_pairs[(size_t)NTAP_O*PAIR_CAP];    // (out_idx, nid) per tap
__device__ int   g_np[NTAP_O];
__device__ float g_cam[N_CAM*24];
__device__ float g_bnscale[PTS_DIM];
__device__ float g_bnbias[PTS_DIM];

// ================= mega kernel 1: transpose + grid init + setup =================
__global__ void mega_setup_kernel(const float* __restrict__ img,
                                  const float* __restrict__ l2i,
                                  const float* __restrict__ iaug,
                                  const float* __restrict__ laug,
                                  const float* __restrict__ gamma,
                                  const float* __restrict__ beta,
                                  const float* __restrict__ mean,
                                  const float* __restrict__ var) {
    int b = blockIdx.x;
    if (b < NB_TRANS) {
        int o = b * 256 + threadIdx.x;
        if (o < TRANS_TOT) {
            int c = o % C_IMG; int rest = o / C_IMG;
            int x = rest % W_FEAT; rest /= W_FEAT;
            int y = rest % H_FEAT; int n = rest / H_FEAT;
            g_imgT[o] = img[(((size_t)n*C_IMG + c)*H_FEAT + y)*W_FEAT + x];
        }
        return;
    }
    b -= NB_TRANS;
    if (b < NB_GRID) {
        int idx = b * 256 + threadIdx.x;
        ((int4*)g_grid)[idx] = make_int4(-1,-1,-1,-1);
        return;
    }
    // setup block
    int t = threadIdx.x;
    if (t < PTS_DIM) {
        float s = rsqrtf(var[t] + 1e-5f) * gamma[t];
        g_bnscale[t] = s;
        g_bnbias[t]  = beta[t] - mean[t] * s;
    }
    if (t >= 128 && t < 128 + NTAP_O) g_np[t-128] = 0;
    if (t == 0) {
        float a0=laug[0],a1=laug[1],a2=laug[2];
        float a3=laug[4],a4=laug[5],a5=laug[6];
        float a6=laug[8],a7=laug[9],a8=laug[10];
        float tx=laug[3], ty=laug[7], tz=laug[11];
        float det = a0*(a4*a8-a5*a7) - a1*(a3*a8-a5*a6) + a2*(a3*a7-a4*a6);
        float id = 1.0f/det;
        float inv[9] = {
            (a4*a8-a5*a7)*id, (a2*a7-a1*a8)*id, (a1*a5-a2*a4)*id,
            (a5*a6-a3*a8)*id, (a0*a8-a2*a6)*id, (a2*a3-a0*a5)*id,
            (a3*a7-a4*a6)*id, (a1*a6-a0*a7)*id, (a0*a4-a1*a3)*id };
        for (int n = 0; n < N_CAM; n++) {
            const float* L = l2i + n*16;
            float P[9], q[3];
            for (int r = 0; r < 3; r++) {
                for (int c = 0; c < 3; c++)
                    P[r*3+c] = L[r*4+0]*inv[0*3+c] + L[r*4+1]*inv[1*3+c] + L[r*4+2]*inv[2*3+c];
                q[r] = L[r*4+3] - (P[r*3+0]*tx + P[r*3+1]*ty + P[r*3+2]*tz);
            }
            float* gc = g_cam + n*24;
            for (int r = 0; r < 3; r++) {
                gc[r*4+0]=P[r*3+0]; gc[r*4+1]=P[r*3+1]; gc[r*4+2]=P[r*3+2]; gc[r*4+3]=q[r];
            }
            const float* A = iaug + n*16;
            for (int r = 0; r < 2; r++) {
                gc[12+r*4+0]=A[r*4+0]; gc[12+r*4+1]=A[r*4+1]; gc[12+r*4+2]=A[r*4+2]; gc[12+r*4+3]=A[r*4+3];
            }
        }
    }
}

// ================= scatter (needs full grid init) =================
__global__ void scatter_kernel(const int* __restrict__ vc) {
    int i = blockIdx.x * 256 + threadIdx.x;
    if (i >= M_PTS) return;
    int4 c4 = ((const int4*)vc)[i];
    int cell = (c4.y*GY + c4.z)*GX + c4.w;
    atomicMax(&g_grid[cell], i);     // last-write-wins (highest index) for duplicates
}

// ================= mega kernel 2: sample + build_pairs + zero_acc =================
__device__ __forceinline__ void sample_body(const int* __restrict__ vc, int blk) {
    int warp = blk * 8 + (threadIdx.x >> 5);
    int lane = threadIdx.x & 31;
    if (warp >= M_PTS) return;
    int4 c4 = ((const int4*)vc)[warp];
    float px = (float)c4.w, py = (float)c4.z, pz = (float)c4.y;
    float4 acc = make_float4(0.f,0.f,0.f,0.f);

    #pragma unroll 1
    for (int n = 0; n < N_CAM; n++) {
        const float* cam = g_cam + n*24;
        float X = cam[0]*px + cam[1]*py + cam[2]*pz  + cam[3];
        float Y = cam[4]*px + cam[5]*py + cam[6]*pz  + cam[7];
        float Z = cam[8]*px + cam[9]*py + cam[10]*pz + cam[11];
        float z = fminf(fmaxf(Z, 1e-5f), 100000.0f);
        float rz = 1.0f / z;
        float vx = X*rz, vy = Y*rz;
        float u = cam[12]*vx + cam[13]*vy + cam[14]*z + cam[15];
        float v = cam[16]*vx + cam[17]*vy + cam[18]*z + cam[19];
        float xf = u * (87.0f/704.0f);
        float yf = v * (31.0f/256.0f);
        float x0 = floorf(xf), y0 = floorf(yf);
        float wx1 = xf - x0, wy1 = yf - y0;
        float wx0 = 1.0f - wx1, wy0 = 1.0f - wy1;

        float cx[4] = {x0, x0+1.0f, x0,      x0+1.0f};
        float cy[4] = {y0, y0,      y0+1.0f, y0+1.0f};
        float cw[4] = {wx0*wy0, wx1*wy0, wx0*wy1, wx1*wy1};
        #pragma unroll
        for (int q = 0; q < 4; q++) {
            if (cx[q] >= 0.0f && cx[q] <= 87.0f && cy[q] >= 0.0f && cy[q] <= 31.0f && lane < 24) {
                const float4* base = (const float4*)(g_imgT +
                    (((size_t)n*H_FEAT + (int)cy[q])*W_FEAT + (int)cx[q]) * C_IMG);
                float4 f = __ldg(base + lane);
                float w = cw[q];
                acc.x += w*f.x; acc.y += w*f.y; acc.z += w*f.z; acc.w += w*f.w;
            }
        }
    }
    if (lane < 24)
        ((float4*)(g_sampled + (size_t)warp*C_IMG))[lane] = acc;
}

// slim build_pairs: warp-ballot + leader global atomic, immediate write (low regs)
__device__ __forceinline__ void build_pairs_body(const int* __restrict__ vc, int blk) {
    int tid = threadIdx.x;
    int i = blk * 256 + tid;
    int lane = tid & 31;
    bool live = i < M_PTS;
    int4 c4 = live ? ((const int4*)vc)[i] : make_int4(0,0,0,0);

    #pragma unroll 1
    for (int t = 0; t < NTAP_O; t++) {
        int k = (t < 13) ? t : t + 1;
        int dz = k/9 - 1, dy = (k/3)%3 - 1, dx = k%3 - 1;
        int nz = c4.y + dz, ny = c4.z + dy, nx = c4.w + dx;
        bool valid = live && nz >= 0 && nz < GZ && ny >= 0 && ny < GY && nx >= 0 && nx < GX;
        int nid = -1;
        if (valid) nid = __ldg(&g_grid[(nz*GY + ny)*GX + nx]);
        valid = valid && (nid >= 0);
        unsigned m = __ballot_sync(0xffffffffu, valid);
        if (m != 0) {
            int ldr = __ffs(m) - 1;
            int base = 0;
            if (lane == ldr) base = atomicAdd(&g_np[t], __popc(m));
            base = __shfl_sync(0xffffffffu, base, ldr);
            if (valid) {
                int rank = __popc(m & ((1u << lane) - 1u));
                g_pairs[(size_t)t*PAIR_CAP + base + rank] = make_int2(i, nid);
            }
        }
    }
}

__global__ void __launch_bounds__(256, 4)
mega_mid_kernel(const int* __restrict__ vc) {
    int b = blockIdx.x;
    if (b < NB_SAMPLE) { sample_body(vc, b); return; }
    b -= NB_SAMPLE;
    if (b < NB_BPAIR)  { build_pairs_body(vc, b); return; }
    b -= NB_BPAIR;
    {
        int idx = b * 256 + threadIdx.x;
        if (idx < (M_PTS*PTS_DIM)/4) ((float4*)g_acc)[idx] = make_float4(0.f,0.f,0.f,0.f);
    }
}

// ---------------- sparse conv: 128x128xK224 register-tiled SGEMM, BK=16, f32x2 ------
template<bool SELF>
__global__ void __launch_bounds__(256, 2)
conv_gemm_kernel(const float* __restrict__ pts,
                 const int*   __restrict__ vc,
                 const float* __restrict__ convw,
                 float*       __restrict__ out) {
    __shared__ float s_a[2][16][128];
    __shared__ float s_b[2][16][128];
    __shared__ int s_out[128];
    __shared__ int s_nid[128];

    int tid = threadIdx.x;
    int k, np, tile0, tstep;
    if (SELF) { k = 13; np = M_PTS; tile0 = blockIdx.x; tstep = NT_SELF; }
    else {
        int t = blockIdx.y;
        k = (t < 13) ? t : t + 1;
        np = g_np[t];
        tile0 = blockIdx.x; tstep = 64;
    }
    const float* wk = convw + (size_t)k*KIN*PTS_DIM;
    const int tpair = SELF ? 0 : (int)blockIdx.y;

    int ty = tid >> 4, tx = tid & 15;       // 16x16 thread grid
    int rowa = tid >> 2, q = tid & 3;       // A loader: rows rowa, rowa+64; k-quad q
    int rowb = tid >> 5;                    // B loader: rows rowb, rowb+8
    int colb = (tid & 31) * 4;

    for (int tile = tile0; tile*128 < np; tile += tstep) {
        __syncthreads();   // protect s_out/s_nid from previous tile epilogue
        int base = tile*128;
        if (tid < 128) {
            int r = base + tid;
            int o = -1, nid = 0;
            if (r < np) {
                if (SELF) {
                    int4 c4 = ((const int4*)vc)[r];
                    o = r;
                    nid = __ldg(&g_grid[(c4.y*GY + c4.z)*GX + c4.w]);
                } else {
                    int2 pr = g_pairs[(size_t)tpair*PAIR_CAP + r];
                    o = pr.x; nid = pr.y;
                }
            }
            s_out[tid] = o;
            s_nid[tid] = nid;
        }
        __syncthreads();

        int nid0 = s_nid[rowa], nid1 = s_nid[rowa + 64];
        const float* a0p = pts       + (size_t)nid0*PTS_DIM + q*4;
        const float* a0s = g_sampled + (size_t)nid0*C_IMG  + q*4;
        const float* a1p = pts       + (size_t)nid1*PTS_DIM + q*4;
        const float* a1s = g_sampled + (size_t)nid1*C_IMG  + q*4;

        u64 acc2[8][4];     // [p][q-pair], 2 output channels per entry
        #pragma unroll
        for (int p = 0; p < 8; p++)
            #pragma unroll
            for (int qq = 0; qq < 4; qq++) acc2[p][qq] = 0ull;

        // preload chunk 0
        float4 av0 = *(const float4*)(a0p);
        float4 av1 = *(const float4*)(a1p);
        float4 bv0 = *(const float4*)(wk + rowb*128 + colb);
        float4 bv1 = *(const float4*)(wk + (rowb+8)*128 + colb);
        {
            s_a[0][q*4+0][rowa] = av0.x;
            s_a[0][q*4+1][rowa] = av0.y;
            s_a[0][q*4+2][rowa] = av0.z;
            s_a[0][q*4+3][rowa] = av0.w;
            s_a[0][q*4+0][rowa+64] = av1.x;
            s_a[0][q*4+1][rowa+64] = av1.y;
            s_a[0][q*4+2][rowa+64] = av1.z;
            s_a[0][q*4+3][rowa+64] = av1.w;
            *(float4*)&s_b[0][rowb][colb]   = bv0;
            *(float4*)&s_b[0][rowb+8][colb] = bv1;
        }
        __syncthreads();

        int buf = 0;
        #pragma unroll 1
        for (int c = 0; c < NCHUNK; c++) {
            if (c + 1 < NCHUNK) {
                int kc0 = (c+1)*16;
                const float* p0 = (kc0 < PTS_DIM) ? (a0p + kc0) : (a0s + (kc0 - PTS_DIM));
                const float* p1 = (kc0 < PTS_DIM) ? (a1p + kc0) : (a1s + (kc0 - PTS_DIM));
                av0 = *(const float4*)p0;
                av1 = *(const float4*)p1;
                bv0 = *(const float4*)(wk + (kc0 + rowb)*128 + colb);
                bv1 = *(const float4*)(wk + (kc0 + rowb+8)*128 + colb);
            }
            #pragma unroll
            for (int kc = 0; kc < 16; kc++) {
                float4 a0 = *(float4*)&s_a[buf][kc][ty*8];
                float4 a1 = *(float4*)&s_a[buf][kc][ty*8+4];
                ulonglong2 bq0 = *(ulonglong2*)&s_b[buf][kc][tx*8];
                ulonglong2 bq1 = *(ulonglong2*)&s_b[buf][kc][tx*8+4];
                u64 b2[4] = {bq0.x, bq0.y, bq1.x, bq1.y};
                float ar[8] = {a0.x,a0.y,a0.z,a0.w,a1.x,a1.y,a1.z,a1.w};
                #pragma unroll
                for (int p = 0; p < 8; p++) {
                    u64 ad;
                    PACK2(ad, ar[p]);
                    FMA2(acc2[p][0], ad, b2[0]);
                    FMA2(acc2[p][1], ad, b2[1]);
                    FMA2(acc2[p][2], ad, b2[2]);
                    FMA2(acc2[p][3], ad, b2[3]);
                }
            }
            if (c + 1 < NCHUNK) {
                int nb = buf ^ 1;
                s_a[nb][q*4+0][rowa] = av0.x;
                s_a[nb][q*4+1][rowa] = av0.y;
                s_a[nb][q*4+2][rowa] = av0.z;
                s_a[nb][q*4+3][rowa] = av0.w;
                s_a[nb][q*4+0][rowa+64] = av1.x;
                s_a[nb][q*4+1][rowa+64] = av1.y;
                s_a[nb][q*4+2][rowa+64] = av1.z;
                s_a[nb][q*4+3][rowa+64] = av1.w;
                *(float4*)&s_b[nb][rowb][colb]   = bv0;
                *(float4*)&s_b[nb][rowb+8][colb] = bv1;
            }
            __syncthreads();
            buf ^= 1;
        }

        // unpack accumulators
        float acc[8][8];
        #pragma unroll
        for (int p = 0; p < 8; p++)
            #pragma unroll
            for (int qq = 0; qq < 4; qq++)
                UNPACK2(acc[p][2*qq], acc[p][2*qq+1], acc2[p][qq]);

        // epilogue
        if (SELF) {
            float sc[8], bi[8];
            #pragma unroll
            for (int qq = 0; qq < 8; qq++) {
                sc[qq] = g_bnscale[tx*8+qq];
                bi[qq] = g_bnbias[tx*8+qq];
            }
            #pragma unroll
            for (int p = 0; p < 8; p++) {
                int o = s_out[ty*8+p];
                if (o >= 0) {
                    const float4* gp = (const float4*)(g_acc + (size_t)o*PTS_DIM + tx*8);
                    float4 g0 = gp[0], g1 = gp[1];
                    float4 r0, r1;
                    r0.x = fmaxf((acc[p][0]+g0.x)*sc[0]+bi[0], 0.f);
                    r0.y = fmaxf((acc[p][1]+g0.y)*sc[1]+bi[1], 0.f);
                    r0.z = fmaxf((acc[p][2]+g0.z)*sc[2]+bi[2], 0.f);
                    r0.w = fmaxf((acc[p][3]+g0.w)*sc[3]+bi[3], 0.f);
                    r1.x = fmaxf((acc[p][4]+g1.x)*sc[4]+bi[4], 0.f);
                    r1.y = fmaxf((acc[p][5]+g1.y)*sc[5]+bi[5], 0.f);
                    r1.z = fmaxf((acc[p][6]+g1.z)*sc[6]+bi[6], 0.f);
                    r1.w = fmaxf((acc[p][7]+g1.w)*sc[7]+bi[7], 0.f);
                    float4* op = (float4*)(out + (size_t)o*PTS_DIM + tx*8);
                    op[0] = r0; op[1] = r1;
                }
            }
        } else {
            #pragma unroll
            for (int p = 0; p < 8; p++) {
                int o = s_out[ty*8+p];
                if (o >= 0) {
                    float* gp = g_acc + (size_t)o*PTS_DIM + tx*8;
                    #pragma unroll
                    for (int qq = 0; qq < 8; qq++)
                        atomicAdd(gp + qq, acc[p][qq]);
                }
            }
        }
    }
}

// ---------------- launch ----------------
extern "C" void kernel_launch(void* const* d_in, const int* in_sizes, int n_in,
                              void* d_out, int out_size) {
    const float* pts   = (const float*)d_in[0];
    const int*   vc    = (const int*)  d_in[1];
    const float* img   = (const float*)d_in[2];
    const float* l2i   = (const float*)d_in[3];
    const float* iaug  = (const float*)d_in[4];
    const float* laug  = (const float*)d_in[5];
    const float* convw = (const float*)d_in[6];
    const float* gamma = (const float*)d_in[7];
    const float* beta  = (const float*)d_in[8];
    const float* mean  = (const float*)d_in[9];
    const float* var   = (const float*)d_in[10];
    float* out = (float*)d_out;

    mega_setup_kernel<<<NB_MEGA1, 256>>>(img, l2i, iaug, laug, gamma, beta, mean, var);
    scatter_kernel<<<(M_PTS + 255)/256, 256>>>(vc);
    mega_mid_kernel<<<NB_MEGA2, 256>>>(vc);
    conv_gemm_kernel<false><<<dim3(64, NTAP_O), 256>>>(pts, vc, convw, out);
    conv_gemm_kernel<true ><<<NT_SELF, 256>>>(pts, vc, convw, out);
}

// round 7
// speedup vs baseline: 1.2009x; 1.0633x over previous
#include <cuda_runtime.h>
#include <cuda_bf16.h>
#include <cstdint>

#define M_PTS   200000
#define N_CAM   6
#define C_IMG   96
#define H_FEAT  32
#define W_FEAT  88
#define PTS_DIM 128
#define KIN     224           // 128 + 96
#define GZ      32
#define GY      512
#define GX      448
#define GRID_N  (GZ*GY*GX)

#define NTAP_O   26
#define PAIR_CAP 200000
#define NCHUNK   14           // 224 / 16

// merged-kernel block dispatch
#define TRANS_TOT  (N_CAM*H_FEAT*W_FEAT*C_IMG)
#define NB_TRANS   ((TRANS_TOT + 255)/256)
#define NB_GRID    (GRID_N/4/256)
#define WT_TOT     (27*KIN*PTS_DIM)
#define NB_WT      ((WT_TOT + 255)/256)
#define NB_SETUP   1
#define NB_MEGA1   (NB_TRANS + NB_GRID + NB_WT + NB_SETUP)

#define NB_SAMPLE  (M_PTS/8)
#define NB_BPAIR   ((M_PTS + 255)/256)
#define NB_ZACC    ((M_PTS*PTS_DIM/4 + 255)/256)
#define NB_MEGA2   (NB_SAMPLE + NB_BPAIR + NB_ZACC)

typedef unsigned u32;

// ---- smem layout for conv (bytes) ----
// B stride: 232 halves (464B) -> conflict-free fragment loads (20g+t pattern)
// A stride: 24 halves (48B)   -> conflict-free (12g+t pattern)
#define B_STRIDE_H 232
#define B_STRIDE_W 116        // u32 stride
#define A_STRIDE_W 12         // u32 stride (24 halves)
#define SM_BHI  0
#define SM_BLO  (128*B_STRIDE_H*2)                 // 59392
#define SM_A    (SM_BLO + 128*B_STRIDE_H*2)        // 118784
#define A_BUF_BYTES (128*A_STRIDE_W*4*2)           // hi+lo per buffer = 12288
#define SMEM_CONV (SM_A + 2*A_BUF_BYTES)           // 143360

// mma.sync m16n8k16 row.col f32.bf16.bf16.f32
#define MMA_BF16(d, a, b0v, b1v) \
    asm volatile("mma.sync.aligned.m16n8k16.row.col.f32.bf16.bf16.f32 " \
        "{%0,%1,%2,%3}, {%4,%5,%6,%7}, {%8,%9}, {%0,%1,%2,%3};" \
        : "+f"((d)[0]), "+f"((d)[1]), "+f"((d)[2]), "+f"((d)[3]) \
        : "r"((a)[0]), "r"((a)[1]), "r"((a)[2]), "r"((a)[3]), "r"(b0v), "r"(b1v))

#define PACK_BF162(r, f0, f1) \
    asm("cvt.rn.bf16x2.f32 %0, %1, %2;" : "=r"(r) : "f"(f1), "f"(f0))   // lo half = f0

// ---------------- device globals ----------------
__device__ float g_imgT[N_CAM*H_FEAT*W_FEAT*C_IMG];
__device__ int   g_grid[GRID_N];
__device__ float g_sampled[(size_t)M_PTS*C_IMG];
__device__ float g_acc[(size_t)M_PTS*PTS_DIM];
__device__ int2  g_pairs[(size_t)NTAP_O*PAIR_CAP];
__device__ int   g_np[NTAP_O];
__device__ float g_cam[N_CAM*24];
__device__ float g_bnscale[PTS_DIM];
__device__ float g_bnbias[PTS_DIM];
__device__ __nv_bfloat16 g_wt_hi[27*PTS_DIM*KIN];   // [k][n][kin]
__device__ __nv_bfloat16 g_wt_lo[27*PTS_DIM*KIN];

// ================= mega kernel 1: transpose + grid init + weight split + setup ============
__global__ void mega_setup_kernel(const float* __restrict__ img,
                                  const float* __restrict__ convw,
                                  const float* __restrict__ l2i,
                                  const float* __restrict__ iaug,
                                  const float* __restrict__ laug,
                                  const float* __restrict__ gamma,
                                  const float* __restrict__ beta,
                                  const float* __restrict__ mean,
                                  const float* __restrict__ var) {
    int b = blockIdx.x;
    if (b < NB_TRANS) {
        int o = b * 256 + threadIdx.x;
        if (o < TRANS_TOT) {
            int c = o % C_IMG; int rest = o / C_IMG;
            int x = rest % W_FEAT; rest /= W_FEAT;
            int y = rest % H_FEAT; int n = rest / H_FEAT;
            g_imgT[o] = img[(((size_t)n*C_IMG + c)*H_FEAT + y)*W_FEAT + x];
        }
        return;
    }
    b -= NB_TRANS;
    if (b < NB_GRID) {
        int idx = b * 256 + threadIdx.x;
        ((int4*)g_grid)[idx] = make_int4(-1,-1,-1,-1);
        return;
    }
    b -= NB_GRID;
    if (b < NB_WT) {
        int o = b * 256 + threadIdx.x;   // o indexes [k][n][kin]
        if (o < WT_TOT) {
            int kin = o % KIN; int rest = o / KIN;
            int n = rest % PTS_DIM; int k = rest / PTS_DIM;
            float w = convw[((size_t)k*KIN + kin)*PTS_DIM + n];
            // truncation split: hi exact prefix, residual exact in fp32
            u32 wb = __float_as_uint(w);
            float hi = __uint_as_float(wb & 0xFFFF0000u);
            float r = w - hi;
            g_wt_hi[o] = __float2bfloat16(hi);
            g_wt_lo[o] = __float2bfloat16(r);
        }
        return;
    }
    // setup block
    int t = threadIdx.x;
    if (t < PTS_DIM) {
        float s = rsqrtf(var[t] + 1e-5f) * gamma[t];
        g_bnscale[t] = s;
        g_bnbias[t]  = beta[t] - mean[t] * s;
    }
    if (t >= 128 && t < 128 + NTAP_O) g_np[t-128] = 0;
    if (t == 0) {
        float a0=laug[0],a1=laug[1],a2=laug[2];
        float a3=laug[4],a4=laug[5],a5=laug[6];
        float a6=laug[8],a7=laug[9],a8=laug[10];
        float tx=laug[3], ty=laug[7], tz=laug[11];
        float det = a0*(a4*a8-a5*a7) - a1*(a3*a8-a5*a6) + a2*(a3*a7-a4*a6);
        float id = 1.0f/det;
        float inv[9] = {
            (a4*a8-a5*a7)*id, (a2*a7-a1*a8)*id, (a1*a5-a2*a4)*id,
            (a5*a6-a3*a8)*id, (a0*a8-a2*a6)*id, (a2*a3-a0*a5)*id,
            (a3*a7-a4*a6)*id, (a1*a6-a0*a7)*id, (a0*a4-a1*a3)*id };
        for (int n = 0; n < N_CAM; n++) {
            const float* L = l2i + n*16;
            float P[9], q[3];
            for (int r = 0; r < 3; r++) {
                for (int c = 0; c < 3; c++)
                    P[r*3+c] = L[r*4+0]*inv[0*3+c] + L[r*4+1]*inv[1*3+c] + L[r*4+2]*inv[2*3+c];
                q[r] = L[r*4+3] - (P[r*3+0]*tx + P[r*3+1]*ty + P[r*3+2]*tz);
            }
            float* gc = g_cam + n*24;
            for (int r = 0; r < 3; r++) {
                gc[r*4+0]=P[r*3+0]; gc[r*4+1]=P[r*3+1]; gc[r*4+2]=P[r*3+2]; gc[r*4+3]=q[r];
            }
            const float* A = iaug + n*16;
            for (int r = 0; r < 2; r++) {
                gc[12+r*4+0]=A[r*4+0]; gc[12+r*4+1]=A[r*4+1]; gc[12+r*4+2]=A[r*4+2]; gc[12+r*4+3]=A[r*4+3];
            }
        }
    }
}

// ================= scatter =================
__global__ void scatter_kernel(const int* __restrict__ vc) {
    int i = blockIdx.x * 256 + threadIdx.x;
    if (i >= M_PTS) return;
    int4 c4 = ((const int4*)vc)[i];
    atomicMax(&g_grid[(c4.y*GY + c4.z)*GX + c4.w], i);
}

// ================= mega kernel 2: sample + build_pairs + zero_acc =================
__device__ __forceinline__ void sample_body(const int* __restrict__ vc, int blk) {
    int warp = blk * 8 + (threadIdx.x >> 5);
    int lane = threadIdx.x & 31;
    if (warp >= M_PTS) return;
    int4 c4 = ((const int4*)vc)[warp];
    float px = (float)c4.w, py = (float)c4.z, pz = (float)c4.y;
    float4 acc = make_float4(0.f,0.f,0.f,0.f);

    #pragma unroll 1
    for (int n = 0; n < N_CAM; n++) {
        const float* cam = g_cam + n*24;
        float X = cam[0]*px + cam[1]*py + cam[2]*pz  + cam[3];
        float Y = cam[4]*px + cam[5]*py + cam[6]*pz  + cam[7];
        float Z = cam[8]*px + cam[9]*py + cam[10]*pz + cam[11];
        float z = fminf(fmaxf(Z, 1e-5f), 100000.0f);
        float rz = 1.0f / z;
        float vx = X*rz, vy = Y*rz;
        float u = cam[12]*vx + cam[13]*vy + cam[14]*z + cam[15];
        float v = cam[16]*vx + cam[17]*vy + cam[18]*z + cam[19];
        float xf = u * (87.0f/704.0f);
        float yf = v * (31.0f/256.0f);
        float x0 = floorf(xf), y0 = floorf(yf);
        float wx1 = xf - x0, wy1 = yf - y0;
        float wx0 = 1.0f - wx1, wy0 = 1.0f - wy1;

        float cx[4] = {x0, x0+1.0f, x0,      x0+1.0f};
        float cy[4] = {y0, y0,      y0+1.0f, y0+1.0f};
        float cw[4] = {wx0*wy0, wx1*wy0, wx0*wy1, wx1*wy1};
        #pragma unroll
        for (int q = 0; q < 4; q++) {
            if (cx[q] >= 0.0f && cx[q] <= 87.0f && cy[q] >= 0.0f && cy[q] <= 31.0f && lane < 24) {
                const float4* base = (const float4*)(g_imgT +
                    (((size_t)n*H_FEAT + (int)cy[q])*W_FEAT + (int)cx[q]) * C_IMG);
                float4 f = __ldg(base + lane);
                float w = cw[q];
                acc.x += w*f.x; acc.y += w*f.y; acc.z += w*f.z; acc.w += w*f.w;
            }
        }
    }
    if (lane < 24)
        ((float4*)(g_sampled + (size_t)warp*C_IMG))[lane] = acc;
}

__device__ __forceinline__ void build_pairs_body(const int* __restrict__ vc, int blk) {
    int tid = threadIdx.x;
    int i = blk * 256 + tid;
    int lane = tid & 31;
    bool live = i < M_PTS;
    int4 c4 = live ? ((const int4*)vc)[i] : make_int4(0,0,0,0);

    #pragma unroll 1
    for (int t = 0; t < NTAP_O; t++) {
        int k = (t < 13) ? t : t + 1;
        int dz = k/9 - 1, dy = (k/3)%3 - 1, dx = k%3 - 1;
        int nz = c4.y + dz, ny = c4.z + dy, nx = c4.w + dx;
        bool valid = live && nz >= 0 && nz < GZ && ny >= 0 && ny < GY && nx >= 0 && nx < GX;
        int nid = -1;
        if (valid) nid = __ldg(&g_grid[(nz*GY + ny)*GX + nx]);
        valid = valid && (nid >= 0);
        unsigned m = __ballot_sync(0xffffffffu, valid);
        if (m != 0) {
            int ldr = __ffs(m) - 1;
            int base = 0;
            if (lane == ldr) base = atomicAdd(&g_np[t], __popc(m));
            base = __shfl_sync(0xffffffffu, base, ldr);
            if (valid) {
                int rank = __popc(m & ((1u << lane) - 1u));
                g_pairs[(size_t)t*PAIR_CAP + base + rank] = make_int2(i, nid);
            }
        }
    }
}

__global__ void __launch_bounds__(256, 4)
mega_mid_kernel(const int* __restrict__ vc) {
    int b = blockIdx.x;
    if (b < NB_SAMPLE) { sample_body(vc, b); return; }
    b -= NB_SAMPLE;
    if (b < NB_BPAIR)  { build_pairs_body(vc, b); return; }
    b -= NB_BPAIR;
    {
        int idx = b * 256 + threadIdx.x;
        if (idx < (M_PTS*PTS_DIM)/4) ((float4*)g_acc)[idx] = make_float4(0.f,0.f,0.f,0.f);
    }
}

// ============ sparse conv via mma.sync bf16-split (3 passes, fp32 accumulate) ============
template<bool SELF>
__global__ void __launch_bounds__(256, 1)
conv_mma_kernel(const float* __restrict__ pts,
                const int*   __restrict__ vc,
                float*       __restrict__ out) {
    extern __shared__ char smem[];
    u32* s_bhi = (u32*)(smem + SM_BHI);
    u32* s_blo = (u32*)(smem + SM_BLO);
    __shared__ int s_out[128];
    __shared__ int s_nid[128];
    __shared__ float s_sc[128], s_bi[128];

    int tid = threadIdx.x;
    int wid = tid >> 5;
    int lane = tid & 31;
    int g = lane >> 2, t = lane & 3;
    int warpRow = (wid >> 1) * 32;
    int warpCol = (wid & 1) * 64;

    int k, np, tile0, tstep, tpair;
    if (SELF) { k = 13; np = M_PTS; tile0 = blockIdx.x; tstep = gridDim.x; tpair = 0; }
    else {
        int tt = blockIdx.y;
        k = (tt < 13) ? tt : tt + 1;
        np = g_np[tt];
        tile0 = blockIdx.x; tstep = gridDim.x; tpair = tt;
    }

    // load B hi/lo into smem [n][kin], stride 116 u32
    {
        const u32* src_h = (const u32*)(g_wt_hi + (size_t)k*PTS_DIM*KIN);
        const u32* src_l = (const u32*)(g_wt_lo + (size_t)k*PTS_DIM*KIN);
        for (int i = tid; i < 128*112; i += 256) {
            int n = i / 112, kp = i % 112;
            s_bhi[n*B_STRIDE_W + kp] = __ldg(src_h + i);
            s_blo[n*B_STRIDE_W + kp] = __ldg(src_l + i);
        }
        if (SELF && tid < 128) { s_sc[tid] = g_bnscale[tid]; s_bi[tid] = g_bnbias[tid]; }
    }
    __syncthreads();

    int grow = tid >> 1, gh = tid & 1;   // gather: 2 threads per row, 8 floats each

    for (int tile = tile0; tile*128 < np; tile += tstep) {
        __syncthreads();
        // tile metadata
        if (tid < 128) {
            int r = tile*128 + tid;
            int o = -1, nid = 0;
            if (r < np) {
                if (SELF) {
                    int4 c4 = ((const int4*)vc)[r];
                    o = r;
                    nid = __ldg(&g_grid[(c4.y*GY + c4.z)*GX + c4.w]);
                } else {
                    int2 pr = g_pairs[(size_t)tpair*PAIR_CAP + r];
                    o = pr.x; nid = pr.y;
                }
            }
            s_out[tid] = o;
            s_nid[tid] = nid;
        }
        __syncthreads();

        int mynid = s_nid[grow];
        const float* rowp = pts       + (size_t)mynid*PTS_DIM + gh*8;
        const float* rows = g_sampled + (size_t)mynid*C_IMG  + gh*8;

        float acc[2][8][4];
        #pragma unroll
        for (int mi = 0; mi < 2; mi++)
            #pragma unroll
            for (int ni = 0; ni < 8; ni++)
                #pragma unroll
                for (int j = 0; j < 4; j++) acc[mi][ni][j] = 0.0f;

        // gather+convert chunk 0 into buf 0
        {
            const float4* src = (const float4*)rowp;
            float4 v0 = __ldg(src), v1 = __ldg(src + 1);
            float f[8] = {v0.x,v0.y,v0.z,v0.w,v1.x,v1.y,v1.z,v1.w};
            u32* ah = (u32*)(smem + SM_A);
            u32* al = (u32*)(smem + SM_A + A_BUF_BYTES/2);
            int base = grow*A_STRIDE_W + gh*4;
            #pragma unroll
            for (int j = 0; j < 4; j++) {
                float f0 = f[2*j], f1 = f[2*j+1];
                u32 b0 = __float_as_uint(f0), b1 = __float_as_uint(f1);
                u32 hiw = (b1 & 0xFFFF0000u) | (b0 >> 16);
                float l0 = f0 - __uint_as_float(b0 & 0xFFFF0000u);
                float l1 = f1 - __uint_as_float(b1 & 0xFFFF0000u);
                u32 low; PACK_BF162(low, l0, l1);
                ah[base + j] = hiw;
                al[base + j] = low;
            }
        }
        __syncthreads();

        #pragma unroll 1
        for (int c = 0; c < NCHUNK; c++) {
            // issue next chunk's global loads
            float4 v0, v1;
            if (c + 1 < NCHUNK) {
                int k0 = (c+1)*16;
                const float4* src = (k0 < PTS_DIM) ? (const float4*)(rowp + k0)
                                                   : (const float4*)(rows + (k0 - PTS_DIM));
                v0 = __ldg(src); v1 = __ldg(src + 1);
            }

            // MMA on buffer c&1
            {
                const u32* ah = (const u32*)(smem + SM_A + (c & 1)*A_BUF_BYTES);
                const u32* al = ah + A_BUF_BYTES/8;   // +6144B = 1536 u32
                u32 fa_h[2][4], fa_l[2][4];
                #pragma unroll
                for (int mi = 0; mi < 2; mi++) {
                    int r0 = (warpRow + mi*16 + g)*A_STRIDE_W;
                    int r1 = r0 + 8*A_STRIDE_W;
                    fa_h[mi][0] = ah[r0 + t];     fa_h[mi][1] = ah[r1 + t];
                    fa_h[mi][2] = ah[r0 + t + 4]; fa_h[mi][3] = ah[r1 + t + 4];
                    fa_l[mi][0] = al[r0 + t];     fa_l[mi][1] = al[r1 + t];
                    fa_l[mi][2] = al[r0 + t + 4]; fa_l[mi][3] = al[r1 + t + 4];
                }
                int koff = c*8 + t;
                #pragma unroll
                for (int ni = 0; ni < 8; ni++) {
                    int n = warpCol + ni*8 + g;
                    u32 bh0 = s_bhi[n*B_STRIDE_W + koff];
                    u32 bh1 = s_bhi[n*B_STRIDE_W + koff + 4];
                    u32 bl0 = s_blo[n*B_STRIDE_W + koff];
                    u32 bl1 = s_blo[n*B_STRIDE_W + koff + 4];
                    #pragma unroll
                    for (int mi = 0; mi < 2; mi++) {
                        MMA_BF16(acc[mi][ni], fa_h[mi], bh0, bh1);
                        MMA_BF16(acc[mi][ni], fa_h[mi], bl0, bl1);
                        MMA_BF16(acc[mi][ni], fa_l[mi], bh0, bh1);
                    }
                }
            }

            // convert+store next chunk into buffer (c+1)&1
            if (c + 1 < NCHUNK) {
                u32* ah = (u32*)(smem + SM_A + ((c+1) & 1)*A_BUF_BYTES);
                u32* al = ah + A_BUF_BYTES/8;
                float f[8] = {v0.x,v0.y,v0.z,v0.w,v1.x,v1.y,v1.z,v1.w};
                int base = grow*A_STRIDE_W + gh*4;
                #pragma unroll
                for (int j = 0; j < 4; j++) {
                    float f0 = f[2*j], f1 = f[2*j+1];
                    u32 b0 = __float_as_uint(f0), b1 = __float_as_uint(f1);
                    u32 hiw = (b1 & 0xFFFF0000u) | (b0 >> 16);
                    float l0 = f0 - __uint_as_float(b0 & 0xFFFF0000u);
                    float l1 = f1 - __uint_as_float(b1 & 0xFFFF0000u);
                    u32 low; PACK_BF162(low, l0, l1);
                    ah[base + j] = hiw;
                    al[base + j] = low;
                }
            }
            __syncthreads();
        }

        // epilogue from registers
        #pragma unroll
        for (int mi = 0; mi < 2; mi++) {
            int r0 = warpRow + mi*16 + g;
            int o0 = s_out[r0], o1 = s_out[r0 + 8];
            #pragma unroll
            for (int ni = 0; ni < 8; ni++) {
                int n0 = warpCol + ni*8 + t*2;
                if (SELF) {
                    float sc0 = s_sc[n0], sc1 = s_sc[n0+1];
                    float bi0 = s_bi[n0], bi1 = s_bi[n0+1];
                    if (o0 >= 0) {
                        float a0 = g_acc[(size_t)o0*PTS_DIM + n0];
                        float a1 = g_acc[(size_t)o0*PTS_DIM + n0 + 1];
                        out[(size_t)o0*PTS_DIM + n0]     = fmaxf((acc[mi][ni][0]+a0)*sc0+bi0, 0.f);
                        out[(size_t)o0*PTS_DIM + n0 + 1] = fmaxf((acc[mi][ni][1]+a1)*sc1+bi1, 0.f);
                    }
                    if (o1 >= 0) {
                        float a2 = g_acc[(size_t)o1*PTS_DIM + n0];
                        float a3 = g_acc[(size_t)o1*PTS_DIM + n0 + 1];
                        out[(size_t)o1*PTS_DIM + n0]     = fmaxf((acc[mi][ni][2]+a2)*sc0+bi0, 0.f);
                        out[(size_t)o1*PTS_DIM + n0 + 1] = fmaxf((acc[mi][ni][3]+a3)*sc1+bi1, 0.f);
                    }
                } else {
                    if (o0 >= 0) {
                        atomicAdd(&g_acc[(size_t)o0*PTS_DIM + n0],     acc[mi][ni][0]);
                        atomicAdd(&g_acc[(size_t)o0*PTS_DIM + n0 + 1], acc[mi][ni][1]);
                    }
                    if (o1 >= 0) {
                        atomicAdd(&g_acc[(size_t)o1*PTS_DIM + n0],     acc[mi][ni][2]);
                        atomicAdd(&g_acc[(size_t)o1*PTS_DIM + n0 + 1], acc[mi][ni][3]);
                    }
                }
            }
        }
    }
}

// ---------------- launch ----------------
extern "C" void kernel_launch(void* const* d_in, const int* in_sizes, int n_in,
                              void* d_out, int out_size) {
    const float* pts   = (const float*)d_in[0];
    const int*   vc    = (const int*)  d_in[1];
    const float* img   = (const float*)d_in[2];
    const float* l2i   = (const float*)d_in[3];
    const float* iaug  = (const float*)d_in[4];
    const float* laug  = (const float*)d_in[5];
    const float* convw = (const float*)d_in[6];
    const float* gamma = (const float*)d_in[7];
    const float* beta  = (const float*)d_in[8];
    const float* mean  = (const float*)d_in[9];
    const float* var   = (const float*)d_in[10];
    float* out = (float*)d_out;

    cudaFuncSetAttribute(conv_mma_kernel<false>, cudaFuncAttributeMaxDynamicSharedMemorySize, SMEM_CONV);
    cudaFuncSetAttribute(conv_mma_kernel<true>,  cudaFuncAttributeMaxDynamicSharedMemorySize, SMEM_CONV);

    mega_setup_kernel<<<NB_MEGA1, 256>>>(img, convw, l2i, iaug, laug, gamma, beta, mean, var);
    scatter_kernel<<<(M_PTS + 255)/256, 256>>>(vc);
    mega_mid_kernel<<<NB_MEGA2, 256>>>(vc);
    conv_mma_kernel<false><<<dim3(6, NTAP_O), 256, SMEM_CONV>>>(pts, vc, out);
    conv_mma_kernel<true ><<<dim3(148, 1),    256, SMEM_CONV>>>(pts, vc, out);
}

// round 8
// speedup vs baseline: 1.2221x; 1.0176x over previous
#include <cuda_runtime.h>
#include <cuda_bf16.h>
#include <cstdint>

#define M_PTS   200000
#define N_CAM   6
#define C_IMG   96
#define H_FEAT  32
#define W_FEAT  88
#define PTS_DIM 128
#define KIN     224           // 128 + 96
#define GZ      32
#define GY      512
#define GX      448
#define GRID_N  (GZ*GY*GX)

#define NTAP_O   26
#define PAIR_CAP 200000
#define NCHUNK   14           // 224 / 16

// merged-kernel block dispatch
#define TRANS_TOT  (N_CAM*H_FEAT*W_FEAT*C_IMG)
#define NB_TRANS   ((TRANS_TOT + 255)/256)
#define NB_GRID    (GRID_N/4/256)
#define WT_TOT     (27*KIN*PTS_DIM)
#define NB_WT      ((WT_TOT + 255)/256)
#define NB_SETUP   1
#define NB_MEGA1   (NB_TRANS + NB_GRID + NB_WT + NB_SETUP)

#define NB_SAMPLE  (M_PTS/8)
#define NB_BPAIR   ((M_PTS + 255)/256)
#define NB_ZACC    ((M_PTS*PTS_DIM/4 + 255)/256)
#define NB_MEGA2   (NB_SAMPLE + NB_BPAIR + NB_ZACC)

typedef unsigned u32;

// ---- conv smem: B hi/lo only, stride 232 halves (conflict-free fragment loads) ----
#define B_STRIDE_H 232
#define B_STRIDE_W 116
#define SM_BHI  0
#define SM_BLO  (128*B_STRIDE_H*2)                 // 59392
#define SMEM_CONV (SM_BLO + 128*B_STRIDE_H*2)      // 118784

// mma.sync m16n8k16 row.col f32.bf16.bf16.f32
#define MMA_BF16(d, a, b0v, b1v) \
    asm volatile("mma.sync.aligned.m16n8k16.row.col.f32.bf16.bf16.f32 " \
        "{%0,%1,%2,%3}, {%4,%5,%6,%7}, {%8,%9}, {%0,%1,%2,%3};" \
        : "+f"((d)[0]), "+f"((d)[1]), "+f"((d)[2]), "+f"((d)[3]) \
        : "r"((a)[0]), "r"((a)[1]), "r"((a)[2]), "r"((a)[3]), "r"(b0v), "r"(b1v))

#define PACK_BF162(r, f0, f1) \
    asm("cvt.rn.bf16x2.f32 %0, %1, %2;" : "=r"(r) : "f"(f1), "f"(f0))   // lo half = f0

// truncation split of a float pair into hi bf16x2 (exact prefix) + lo bf16x2 (rn residual)
__device__ __forceinline__ void split2(float x, float y, u32& hi, u32& lo) {
    u32 b0 = __float_as_uint(x), b1 = __float_as_uint(y);
    hi = (b1 & 0xFFFF0000u) | (b0 >> 16);
    float l0 = x - __uint_as_float(b0 & 0xFFFF0000u);
    float l1 = y - __uint_as_float(b1 & 0xFFFF0000u);
    PACK_BF162(lo, l0, l1);
}

// ---------------- device globals ----------------
__device__ float g_imgT[N_CAM*H_FEAT*W_FEAT*C_IMG];
__device__ int   g_grid[GRID_N];
__device__ float g_sampled[(size_t)M_PTS*C_IMG];
__device__ float g_acc[(size_t)M_PTS*PTS_DIM];
__device__ int2  g_pairs[(size_t)NTAP_O*PAIR_CAP];
__device__ int   g_np[NTAP_O];
__device__ float g_cam[N_CAM*24];
__device__ float g_bnscale[PTS_DIM];
__device__ float g_bnbias[PTS_DIM];
__device__ __nv_bfloat16 g_wt_hi[27*PTS_DIM*KIN];   // [k][n][kin]
__device__ __nv_bfloat16 g_wt_lo[27*PTS_DIM*KIN];

// ================= mega kernel 1: transpose + grid init + weight split + setup ============
__global__ void mega_setup_kernel(const float* __restrict__ img,
                                  const float* __restrict__ convw,
                                  const float* __restrict__ l2i,
                                  const float* __restrict__ iaug,
                                  const float* __restrict__ laug,
                                  const float* __restrict__ gamma,
                                  const float* __restrict__ beta,
                                  const float* __restrict__ mean,
                                  const float* __restrict__ var) {
    int b = blockIdx.x;
    if (b < NB_TRANS) {
        int o = b * 256 + threadIdx.x;
        if (o < TRANS_TOT) {
            int c = o % C_IMG; int rest = o / C_IMG;
            int x = rest % W_FEAT; rest /= W_FEAT;
            int y = rest % H_FEAT; int n = rest / H_FEAT;
            g_imgT[o] = img[(((size_t)n*C_IMG + c)*H_FEAT + y)*W_FEAT + x];
        }
        return;
    }
    b -= NB_TRANS;
    if (b < NB_GRID) {
        int idx = b * 256 + threadIdx.x;
        ((int4*)g_grid)[idx] = make_int4(-1,-1,-1,-1);
        return;
    }
    b -= NB_GRID;
    if (b < NB_WT) {
        int o = b * 256 + threadIdx.x;   // o indexes [k][n][kin]
        if (o < WT_TOT) {
            int kin = o % KIN; int rest = o / KIN;
            int n = rest % PTS_DIM; int k = rest / PTS_DIM;
            float w = convw[((size_t)k*KIN + kin)*PTS_DIM + n];
            u32 wb = __float_as_uint(w);
            float hi = __uint_as_float(wb & 0xFFFF0000u);
            float r = w - hi;
            g_wt_hi[o] = __float2bfloat16(hi);
            g_wt_lo[o] = __float2bfloat16(r);
        }
        return;
    }
    // setup block
    int t = threadIdx.x;
    if (t < PTS_DIM) {
        float s = rsqrtf(var[t] + 1e-5f) * gamma[t];
        g_bnscale[t] = s;
        g_bnbias[t]  = beta[t] - mean[t] * s;
    }
    if (t >= 128 && t < 128 + NTAP_O) g_np[t-128] = 0;
    if (t == 0) {
        float a0=laug[0],a1=laug[1],a2=laug[2];
        float a3=laug[4],a4=laug[5],a5=laug[6];
        float a6=laug[8],a7=laug[9],a8=laug[10];
        float tx=laug[3], ty=laug[7], tz=laug[11];
        float det = a0*(a4*a8-a5*a7) - a1*(a3*a8-a5*a6) + a2*(a3*a7-a4*a6);
        float id = 1.0f/det;
        float inv[9] = {
            (a4*a8-a5*a7)*id, (a2*a7-a1*a8)*id, (a1*a5-a2*a4)*id,
            (a5*a6-a3*a8)*id, (a0*a8-a2*a6)*id, (a2*a3-a0*a5)*id,
            (a3*a7-a4*a6)*id, (a1*a6-a0*a7)*id, (a0*a4-a1*a3)*id };
        for (int n = 0; n < N_CAM; n++) {
            const float* L = l2i + n*16;
            float P[9], q[3];
            for (int r = 0; r < 3; r++) {
                for (int c = 0; c < 3; c++)
                    P[r*3+c] = L[r*4+0]*inv[0*3+c] + L[r*4+1]*inv[1*3+c] + L[r*4+2]*inv[2*3+c];
                q[r] = L[r*4+3] - (P[r*3+0]*tx + P[r*3+1]*ty + P[r*3+2]*tz);
            }
            float* gc = g_cam + n*24;
            for (int r = 0; r < 3; r++) {
                gc[r*4+0]=P[r*3+0]; gc[r*4+1]=P[r*3+1]; gc[r*4+2]=P[r*3+2]; gc[r*4+3]=q[r];
            }
            const float* A = iaug + n*16;
            for (int r = 0; r < 2; r++) {
                gc[12+r*4+0]=A[r*4+0]; gc[12+r*4+1]=A[r*4+1]; gc[12+r*4+2]=A[r*4+2]; gc[12+r*4+3]=A[r*4+3];
            }
        }
    }
}

// ================= scatter =================
__global__ void scatter_kernel(const int* __restrict__ vc) {
    int i = blockIdx.x * 256 + threadIdx.x;
    if (i >= M_PTS) return;
    int4 c4 = ((const int4*)vc)[i];
    atomicMax(&g_grid[(c4.y*GY + c4.z)*GX + c4.w], i);
}

// ================= mega kernel 2: sample + build_pairs + zero_acc =================
__device__ __forceinline__ void sample_body(const int* __restrict__ vc, int blk) {
    int warp = blk * 8 + (threadIdx.x >> 5);
    int lane = threadIdx.x & 31;
    if (warp >= M_PTS) return;
    int4 c4 = ((const int4*)vc)[warp];
    float px = (float)c4.w, py = (float)c4.z, pz = (float)c4.y;
    float4 acc = make_float4(0.f,0.f,0.f,0.f);

    #pragma unroll 1
    for (int n = 0; n < N_CAM; n++) {
        const float* cam = g_cam + n*24;
        float X = cam[0]*px + cam[1]*py + cam[2]*pz  + cam[3];
        float Y = cam[4]*px + cam[5]*py + cam[6]*pz  + cam[7];
        float Z = cam[8]*px + cam[9]*py + cam[10]*pz + cam[11];
        float z = fminf(fmaxf(Z, 1e-5f), 100000.0f);
        float rz = 1.0f / z;
        float vx = X*rz, vy = Y*rz;
        float u = cam[12]*vx + cam[13]*vy + cam[14]*z + cam[15];
        float v = cam[16]*vx + cam[17]*vy + cam[18]*z + cam[19];
        float xf = u * (87.0f/704.0f);
        float yf = v * (31.0f/256.0f);
        float x0 = floorf(xf), y0 = floorf(yf);
        float wx1 = xf - x0, wy1 = yf - y0;
        float wx0 = 1.0f - wx1, wy0 = 1.0f - wy1;

        float cx[4] = {x0, x0+1.0f, x0,      x0+1.0f};
        float cy[4] = {y0, y0,      y0+1.0f, y0+1.0f};
        float cw[4] = {wx0*wy0, wx1*wy0, wx0*wy1, wx1*wy1};
        #pragma unroll
        for (int q = 0; q < 4; q++) {
            if (cx[q] >= 0.0f && cx[q] <= 87.0f && cy[q] >= 0.0f && cy[q] <= 31.0f && lane < 24) {
                const float4* base = (const float4*)(g_imgT +
                    (((size_t)n*H_FEAT + (int)cy[q])*W_FEAT + (int)cx[q]) * C_IMG);
                float4 f = __ldg(base + lane);
                float w = cw[q];
                acc.x += w*f.x; acc.y += w*f.y; acc.z += w*f.z; acc.w += w*f.w;
            }
        }
    }
    if (lane < 24)
        ((float4*)(g_sampled + (size_t)warp*C_IMG))[lane] = acc;
}

__device__ __forceinline__ void build_pairs_body(const int* __restrict__ vc, int blk) {
    int tid = threadIdx.x;
    int i = blk * 256 + tid;
    int lane = tid & 31;
    bool live = i < M_PTS;
    int4 c4 = live ? ((const int4*)vc)[i] : make_int4(0,0,0,0);

    #pragma unroll 1
    for (int t = 0; t < NTAP_O; t++) {
        int k = (t < 13) ? t : t + 1;
        int dz = k/9 - 1, dy = (k/3)%3 - 1, dx = k%3 - 1;
        int nz = c4.y + dz, ny = c4.z + dy, nx = c4.w + dx;
        bool valid = live && nz >= 0 && nz < GZ && ny >= 0 && ny < GY && nx >= 0 && nx < GX;
        int nid = -1;
        if (valid) nid = __ldg(&g_grid[(nz*GY + ny)*GX + nx]);
        valid = valid && (nid >= 0);
        unsigned m = __ballot_sync(0xffffffffu, valid);
        if (m != 0) {
            int ldr = __ffs(m) - 1;
            int base = 0;
            if (lane == ldr) base = atomicAdd(&g_np[t], __popc(m));
            base = __shfl_sync(0xffffffffu, base, ldr);
            if (valid) {
                int rank = __popc(m & ((1u << lane) - 1u));
                g_pairs[(size_t)t*PAIR_CAP + base + rank] = make_int2(i, nid);
            }
        }
    }
}

__global__ void __launch_bounds__(256, 4)
mega_mid_kernel(const int* __restrict__ vc) {
    int b = blockIdx.x;
    if (b < NB_SAMPLE) { sample_body(vc, b); return; }
    b -= NB_SAMPLE;
    if (b < NB_BPAIR)  { build_pairs_body(vc, b); return; }
    b -= NB_BPAIR;
    {
        int idx = b * 256 + threadIdx.x;
        if (idx < (M_PTS*PTS_DIM)/4) ((float4*)g_acc)[idx] = make_float4(0.f,0.f,0.f,0.f);
    }
}

// ============ sparse conv via mma.sync bf16-split — barrier-free mainloop ============
// A fragments built directly in registers from global (L1-cached row reuse).
template<bool SELF>
__global__ void __launch_bounds__(256, 1)
conv_mma_kernel(const float* __restrict__ pts,
                const int*   __restrict__ vc,
                float*       __restrict__ out) {
    extern __shared__ char smem[];
    u32* s_bhi = (u32*)(smem + SM_BHI);
    u32* s_blo = (u32*)(smem + SM_BLO);
    __shared__ int s_out[128];
    __shared__ int s_nid[128];
    __shared__ float s_sc[128], s_bi[128];

    int tid = threadIdx.x;
    int wid = tid >> 5;
    int lane = tid & 31;
    int g = lane >> 2, t = lane & 3;
    int warpRow = (wid >> 1) * 32;
    int warpCol = (wid & 1) * 64;

    int k, np, tile0, tstep, tpair;
    if (SELF) { k = 13; np = M_PTS; tile0 = blockIdx.x; tstep = gridDim.x; tpair = 0; }
    else {
        int tt = blockIdx.y;
        k = (tt < 13) ? tt : tt + 1;
        np = g_np[tt];
        tile0 = blockIdx.x; tstep = gridDim.x; tpair = tt;
    }

    // load B hi/lo into smem [n][kin]
    {
        const u32* src_h = (const u32*)(g_wt_hi + (size_t)k*PTS_DIM*KIN);
        const u32* src_l = (const u32*)(g_wt_lo + (size_t)k*PTS_DIM*KIN);
        for (int i = tid; i < 128*112; i += 256) {
            int n = i / 112, kp = i % 112;
            s_bhi[n*B_STRIDE_W + kp] = __ldg(src_h + i);
            s_blo[n*B_STRIDE_W + kp] = __ldg(src_l + i);
        }
        if (SELF && tid < 128) { s_sc[tid] = g_bnscale[tid]; s_bi[tid] = g_bnbias[tid]; }
    }
    __syncthreads();

    for (int tile = tile0; tile*128 < np; tile += tstep) {
        __syncthreads();
        // tile metadata
        if (tid < 128) {
            int r = tile*128 + tid;
            int o = -1, nid = 0;
            if (r < np) {
                if (SELF) {
                    int4 c4 = ((const int4*)vc)[r];
                    o = r;
                    nid = __ldg(&g_grid[(c4.y*GY + c4.z)*GX + c4.w]);
                } else {
                    int2 pr = g_pairs[(size_t)tpair*PAIR_CAP + r];
                    o = pr.x; nid = pr.y;
                }
            }
            s_out[tid] = o;
            s_nid[tid] = nid;
        }
        __syncthreads();

        // my 4 A rows (mi0: g, g+8 ; mi1: g+16, g+24)
        int nidr[4];
        nidr[0] = s_nid[warpRow + g];
        nidr[1] = s_nid[warpRow + g + 8];
        nidr[2] = s_nid[warpRow + g + 16];
        nidr[3] = s_nid[warpRow + g + 24];
        const float* rp[4]; const float* rs[4];
        #pragma unroll
        for (int r = 0; r < 4; r++) {
            rp[r] = pts       + (size_t)nidr[r]*PTS_DIM + 2*t;
            rs[r] = g_sampled + (size_t)nidr[r]*C_IMG  + 2*t;
        }

        float acc[2][8][4];
        #pragma unroll
        for (int mi = 0; mi < 2; mi++)
            #pragma unroll
            for (int ni = 0; ni < 8; ni++)
                #pragma unroll
                for (int j = 0; j < 4; j++) acc[mi][ni][j] = 0.0f;

        // barrier-free mainloop
        #pragma unroll 1
        for (int c = 0; c < NCHUNK; c++) {
            int kb = c * 16;
            u32 fh[4][2], fl[4][2];   // [row][0: k+0..1, 1: k+8..9]
            #pragma unroll
            for (int r = 0; r < 4; r++) {
                const float* base = (kb < PTS_DIM) ? (rp[r] + kb) : (rs[r] + (kb - PTS_DIM));
                float2 v0 = __ldg((const float2*)base);
                float2 v1 = __ldg((const float2*)(base + 8));
                split2(v0.x, v0.y, fh[r][0], fl[r][0]);
                split2(v1.x, v1.y, fh[r][1], fl[r][1]);
            }
            u32 fa_h[2][4] = {{fh[0][0], fh[1][0], fh[0][1], fh[1][1]},
                              {fh[2][0], fh[3][0], fh[2][1], fh[3][1]}};
            u32 fa_l[2][4] = {{fl[0][0], fl[1][0], fl[0][1], fl[1][1]},
                              {fl[2][0], fl[3][0], fl[2][1], fl[3][1]}};

            int koff = c*8 + t;
            #pragma unroll
            for (int ni = 0; ni < 8; ni++) {
                int n = warpCol + ni*8 + g;
                u32 bh0 = s_bhi[n*B_STRIDE_W + koff];
                u32 bh1 = s_bhi[n*B_STRIDE_W + koff + 4];
                u32 bl0 = s_blo[n*B_STRIDE_W + koff];
                u32 bl1 = s_blo[n*B_STRIDE_W + koff + 4];
                #pragma unroll
                for (int mi = 0; mi < 2; mi++) {
                    MMA_BF16(acc[mi][ni], fa_h[mi], bh0, bh1);
                    MMA_BF16(acc[mi][ni], fa_h[mi], bl0, bl1);
                    MMA_BF16(acc[mi][ni], fa_l[mi], bh0, bh1);
                }
            }
        }

        // epilogue from registers
        #pragma unroll
        for (int mi = 0; mi < 2; mi++) {
            int r0 = warpRow + mi*16 + g;
            int o0 = s_out[r0], o1 = s_out[r0 + 8];
            #pragma unroll
            for (int ni = 0; ni < 8; ni++) {
                int n0 = warpCol + ni*8 + t*2;
                if (SELF) {
                    float sc0 = s_sc[n0], sc1 = s_sc[n0+1];
                    float bi0 = s_bi[n0], bi1 = s_bi[n0+1];
                    if (o0 >= 0) {
                        float a0 = g_acc[(size_t)o0*PTS_DIM + n0];
                        float a1 = g_acc[(size_t)o0*PTS_DIM + n0 + 1];
                        out[(size_t)o0*PTS_DIM + n0]     = fmaxf((acc[mi][ni][0]+a0)*sc0+bi0, 0.f);
                        out[(size_t)o0*PTS_DIM + n0 + 1] = fmaxf((acc[mi][ni][1]+a1)*sc1+bi1, 0.f);
                    }
                    if (o1 >= 0) {
                        float a2 = g_acc[(size_t)o1*PTS_DIM + n0];
                        float a3 = g_acc[(size_t)o1*PTS_DIM + n0 + 1];
                        out[(size_t)o1*PTS_DIM + n0]     = fmaxf((acc[mi][ni][2]+a2)*sc0+bi0, 0.f);
                        out[(size_t)o1*PTS_DIM + n0 + 1] = fmaxf((acc[mi][ni][3]+a3)*sc1+bi1, 0.f);
                    }
                } else {
                    if (o0 >= 0) {
                        atomicAdd(&g_acc[(size_t)o0*PTS_DIM + n0],     acc[mi][ni][0]);
                        atomicAdd(&g_acc[(size_t)o0*PTS_DIM + n0 + 1], acc[mi][ni][1]);
                    }
                    if (o1 >= 0) {
                        atomicAdd(&g_acc[(size_t)o1*PTS_DIM + n0],     acc[mi][ni][2]);
                        atomicAdd(&g_acc[(size_t)o1*PTS_DIM + n0 + 1], acc[mi][ni][3]);
                    }
                }
            }
        }
    }
}

// ---------------- launch ----------------
extern "C" void kernel_launch(void* const* d_in, const int* in_sizes, int n_in,
                              void* d_out, int out_size) {
    const float* pts   = (const float*)d_in[0];
    const int*   vc    = (const int*)  d_in[1];
    const float* img   = (const float*)d_in[2];
    const float* l2i   = (const float*)d_in[3];
    const float* iaug  = (const float*)d_in[4];
    const float* laug  = (const float*)d_in[5];
    const float* convw = (const float*)d_in[6];
    const float* gamma = (const float*)d_in[7];
    const float* beta  = (const float*)d_in[8];
    const float* mean  = (const float*)d_in[9];
    const float* var   = (const float*)d_in[10];
    float* out = (float*)d_out;

    cudaFuncSetAttribute(conv_mma_kernel<false>, cudaFuncAttributeMaxDynamicSharedMemorySize, SMEM_CONV);
    cudaFuncSetAttribute(conv_mma_kernel<true>,  cudaFuncAttributeMaxDynamicSharedMemorySize, SMEM_CONV);

    mega_setup_kernel<<<NB_MEGA1, 256>>>(img, convw, l2i, iaug, laug, gamma, beta, mean, var);
    scatter_kernel<<<(M_PTS + 255)/256, 256>>>(vc);
    mega_mid_kernel<<<NB_MEGA2, 256>>>(vc);
    conv_mma_kernel<false><<<dim3(12, NTAP_O), 256, SMEM_CONV>>>(pts, vc, out);
    conv_mma_kernel<true ><<<dim3(148, 1),     256, SMEM_CONV>>>(pts, vc, out);
}

// round 9
// speedup vs baseline: 1.3449x; 1.1004x over previous
#include <cuda_runtime.h>
#include <cuda_bf16.h>
#include <cstdint>

#define M_PTS   200000
#define N_CAM   6
#define C_IMG   96
#define H_FEAT  32
#define W_FEAT  88
#define PTS_DIM 128
#define KIN     224           // 128 + 96
#define GZ      32
#define GY      512
#define GX      448
#define GRID_N  (GZ*GY*GX)

#define NTAP_O   26
#define PAIR_CAP 200000
#define NCHUNK   14           // 224 / 16

// merged-kernel block dispatch
#define TRANS_TOT  (N_CAM*H_FEAT*W_FEAT*C_IMG)
#define NB_TRANS   ((TRANS_TOT + 255)/256)
#define NB_GRID    (GRID_N/4/256)
#define WT_TOT     (27*KIN*PTS_DIM)
#define NB_WT      ((WT_TOT + 255)/256)
#define NB_SETUP   1
#define NB_MEGA1   (NB_TRANS + NB_GRID + NB_WT + NB_SETUP)

#define NB_SAMPLE  (M_PTS/8)
#define NB_BPAIR   ((M_PTS + 255)/256)
#define NB_ZACC    ((M_PTS*PTS_DIM/4 + 255)/256)
#define NB_MEGA2   (NB_SAMPLE + NB_BPAIR + NB_ZACC)

typedef unsigned u32;

// ---- conv smem: B hi/lo only, stride 232 halves (conflict-free fragment loads) ----
#define B_STRIDE_H 232
#define B_STRIDE_W 116
#define SM_BHI  0
#define SM_BLO  (128*B_STRIDE_H*2)                 // 59392
#define SMEM_CONV (SM_BLO + 128*B_STRIDE_H*2)      // 118784

// mma.sync m16n8k16 row.col f32.bf16.bf16.f32
#define MMA_BF16(d, a, b0v, b1v) \
    asm volatile("mma.sync.aligned.m16n8k16.row.col.f32.bf16.bf16.f32 " \
        "{%0,%1,%2,%3}, {%4,%5,%6,%7}, {%8,%9}, {%0,%1,%2,%3};" \
        : "+f"((d)[0]), "+f"((d)[1]), "+f"((d)[2]), "+f"((d)[3]) \
        : "r"((a)[0]), "r"((a)[1]), "r"((a)[2]), "r"((a)[3]), "r"(b0v), "r"(b1v))

#define PACK_BF162(r, f0, f1) \
    asm("cvt.rn.bf16x2.f32 %0, %1, %2;" : "=r"(r) : "f"(f1), "f"(f0))   // lo half = f0

// truncation split of a float pair into hi bf16x2 (exact prefix) + lo bf16x2 (rn residual)
__device__ __forceinline__ void split2(float x, float y, u32& hi, u32& lo) {
    u32 b0 = __float_as_uint(x), b1 = __float_as_uint(y);
    hi = (b1 & 0xFFFF0000u) | (b0 >> 16);
    float l0 = x - __uint_as_float(b0 & 0xFFFF0000u);
    float l1 = y - __uint_as_float(b1 & 0xFFFF0000u);
    PACK_BF162(lo, l0, l1);
}

// ---------------- device globals ----------------
__device__ float g_imgT[N_CAM*H_FEAT*W_FEAT*C_IMG];
__device__ int   g_grid[GRID_N];
__device__ float g_sampled[(size_t)M_PTS*C_IMG];
__device__ float g_acc[(size_t)M_PTS*PTS_DIM];
__device__ int2  g_pairs[(size_t)NTAP_O*PAIR_CAP];
__device__ int   g_np[NTAP_O];
__device__ float g_cam[N_CAM*24];
__device__ float g_bnscale[PTS_DIM];
__device__ float g_bnbias[PTS_DIM];
__device__ __nv_bfloat16 g_wt_hi[27*PTS_DIM*KIN];   // [k][n][kin]
__device__ __nv_bfloat16 g_wt_lo[27*PTS_DIM*KIN];

// ================= mega kernel 1: transpose + grid init + weight split + setup ============
__global__ void mega_setup_kernel(const float* __restrict__ img,
                                  const float* __restrict__ convw,
                                  const float* __restrict__ l2i,
                                  const float* __restrict__ iaug,
                                  const float* __restrict__ laug,
                                  const float* __restrict__ gamma,
                                  const float* __restrict__ beta,
                                  const float* __restrict__ mean,
                                  const float* __restrict__ var) {
    int b = blockIdx.x;
    if (b < NB_TRANS) {
        int o = b * 256 + threadIdx.x;
        if (o < TRANS_TOT) {
            int c = o % C_IMG; int rest = o / C_IMG;
            int x = rest % W_FEAT; rest /= W_FEAT;
            int y = rest % H_FEAT; int n = rest / H_FEAT;
            g_imgT[o] = img[(((size_t)n*C_IMG + c)*H_FEAT + y)*W_FEAT + x];
        }
        return;
    }
    b -= NB_TRANS;
    if (b < NB_GRID) {
        int idx = b * 256 + threadIdx.x;
        ((int4*)g_grid)[idx] = make_int4(-1,-1,-1,-1);
        return;
    }
    b -= NB_GRID;
    if (b < NB_WT) {
        int o = b * 256 + threadIdx.x;   // o indexes [k][n][kin]
        if (o < WT_TOT) {
            int kin = o % KIN; int rest = o / KIN;
            int n = rest % PTS_DIM; int k = rest / PTS_DIM;
            float w = convw[((size_t)k*KIN + kin)*PTS_DIM + n];
            u32 wb = __float_as_uint(w);
            float hi = __uint_as_float(wb & 0xFFFF0000u);
            float r = w - hi;
            g_wt_hi[o] = __float2bfloat16(hi);
            g_wt_lo[o] = __float2bfloat16(r);
        }
        return;
    }
    // setup block
    int t = threadIdx.x;
    if (t < PTS_DIM) {
        float s = rsqrtf(var[t] + 1e-5f) * gamma[t];
        g_bnscale[t] = s;
        g_bnbias[t]  = beta[t] - mean[t] * s;
    }
    if (t >= 128 && t < 128 + NTAP_O) g_np[t-128] = 0;
    if (t == 0) {
        float a0=laug[0],a1=laug[1],a2=laug[2];
        float a3=laug[4],a4=laug[5],a5=laug[6];
        float a6=laug[8],a7=laug[9],a8=laug[10];
        float tx=laug[3], ty=laug[7], tz=laug[11];
        float det = a0*(a4*a8-a5*a7) - a1*(a3*a8-a5*a6) + a2*(a3*a7-a4*a6);
        float id = 1.0f/det;
        float inv[9] = {
            (a4*a8-a5*a7)*id, (a2*a7-a1*a8)*id, (a1*a5-a2*a4)*id,
            (a5*a6-a3*a8)*id, (a0*a8-a2*a6)*id, (a2*a3-a0*a5)*id,
            (a3*a7-a4*a6)*id, (a1*a6-a0*a7)*id, (a0*a4-a1*a3)*id };
        for (int n = 0; n < N_CAM; n++) {
            const float* L = l2i + n*16;
            float P[9], q[3];
            for (int r = 0; r < 3; r++) {
                for (int c = 0; c < 3; c++)
                    P[r*3+c] = L[r*4+0]*inv[0*3+c] + L[r*4+1]*inv[1*3+c] + L[r*4+2]*inv[2*3+c];
                q[r] = L[r*4+3] - (P[r*3+0]*tx + P[r*3+1]*ty + P[r*3+2]*tz);
            }
            float* gc = g_cam + n*24;
            for (int r = 0; r < 3; r++) {
                gc[r*4+0]=P[r*3+0]; gc[r*4+1]=P[r*3+1]; gc[r*4+2]=P[r*3+2]; gc[r*4+3]=q[r];
            }
            const float* A = iaug + n*16;
            for (int r = 0; r < 2; r++) {
                gc[12+r*4+0]=A[r*4+0]; gc[12+r*4+1]=A[r*4+1]; gc[12+r*4+2]=A[r*4+2]; gc[12+r*4+3]=A[r*4+3];
            }
        }
    }
}

// ================= scatter =================
__global__ void scatter_kernel(const int* __restrict__ vc) {
    int i = blockIdx.x * 256 + threadIdx.x;
    if (i >= M_PTS) return;
    int4 c4 = ((const int4*)vc)[i];
    atomicMax(&g_grid[(c4.y*GY + c4.z)*GX + c4.w], i);
}

// ================= mega kernel 2: sample + build_pairs + zero_acc =================
__device__ __forceinline__ void sample_body(const int* __restrict__ vc, int blk) {
    int warp = blk * 8 + (threadIdx.x >> 5);
    int lane = threadIdx.x & 31;
    if (warp >= M_PTS) return;
    int4 c4 = ((const int4*)vc)[warp];
    float px = (float)c4.w, py = (float)c4.z, pz = (float)c4.y;
    float4 acc = make_float4(0.f,0.f,0.f,0.f);

    #pragma unroll 1
    for (int n = 0; n < N_CAM; n++) {
        const float* cam = g_cam + n*24;
        float X = cam[0]*px + cam[1]*py + cam[2]*pz  + cam[3];
        float Y = cam[4]*px + cam[5]*py + cam[6]*pz  + cam[7];
        float Z = cam[8]*px + cam[9]*py + cam[10]*pz + cam[11];
        float z = fminf(fmaxf(Z, 1e-5f), 100000.0f);
        float rz = 1.0f / z;
        float vx = X*rz, vy = Y*rz;
        float u = cam[12]*vx + cam[13]*vy + cam[14]*z + cam[15];
        float v = cam[16]*vx + cam[17]*vy + cam[18]*z + cam[19];
        float xf = u * (87.0f/704.0f);
        float yf = v * (31.0f/256.0f);
        float x0 = floorf(xf), y0 = floorf(yf);
        float wx1 = xf - x0, wy1 = yf - y0;
        float wx0 = 1.0f - wx1, wy0 = 1.0f - wy1;

        float cx[4] = {x0, x0+1.0f, x0,      x0+1.0f};
        float cy[4] = {y0, y0,      y0+1.0f, y0+1.0f};
        float cw[4] = {wx0*wy0, wx1*wy0, wx0*wy1, wx1*wy1};
        #pragma unroll
        for (int q = 0; q < 4; q++) {
            if (cx[q] >= 0.0f && cx[q] <= 87.0f && cy[q] >= 0.0f && cy[q] <= 31.0f && lane < 24) {
                const float4* base = (const float4*)(g_imgT +
                    (((size_t)n*H_FEAT + (int)cy[q])*W_FEAT + (int)cx[q]) * C_IMG);
                float4 f = __ldg(base + lane);
                float w = cw[q];
                acc.x += w*f.x; acc.y += w*f.y; acc.z += w*f.z; acc.w += w*f.w;
            }
        }
    }
    if (lane < 24)
        ((float4*)(g_sampled + (size_t)warp*C_IMG))[lane] = acc;
}

__device__ __forceinline__ void build_pairs_body(const int* __restrict__ vc, int blk) {
    int tid = threadIdx.x;
    int i = blk * 256 + tid;
    int lane = tid & 31;
    bool live = i < M_PTS;
    int4 c4 = live ? ((const int4*)vc)[i] : make_int4(0,0,0,0);

    #pragma unroll 1
    for (int t = 0; t < NTAP_O; t++) {
        int k = (t < 13) ? t : t + 1;
        int dz = k/9 - 1, dy = (k/3)%3 - 1, dx = k%3 - 1;
        int nz = c4.y + dz, ny = c4.z + dy, nx = c4.w + dx;
        bool valid = live && nz >= 0 && nz < GZ && ny >= 0 && ny < GY && nx >= 0 && nx < GX;
        int nid = -1;
        if (valid) nid = __ldg(&g_grid[(nz*GY + ny)*GX + nx]);
        valid = valid && (nid >= 0);
        unsigned m = __ballot_sync(0xffffffffu, valid);
        if (m != 0) {
            int ldr = __ffs(m) - 1;
            int base = 0;
            if (lane == ldr) base = atomicAdd(&g_np[t], __popc(m));
            base = __shfl_sync(0xffffffffu, base, ldr);
            if (valid) {
                int rank = __popc(m & ((1u << lane) - 1u));
                g_pairs[(size_t)t*PAIR_CAP + base + rank] = make_int2(i, nid);
            }
        }
    }
}

__global__ void __launch_bounds__(256, 4)
mega_mid_kernel(const int* __restrict__ vc) {
    int b = blockIdx.x;
    if (b < NB_SAMPLE) { sample_body(vc, b); return; }
    b -= NB_SAMPLE;
    if (b < NB_BPAIR)  { build_pairs_body(vc, b); return; }
    b -= NB_BPAIR;
    {
        int idx = b * 256 + threadIdx.x;
        if (idx < (M_PTS*PTS_DIM)/4) ((float4*)g_acc)[idx] = make_float4(0.f,0.f,0.f,0.f);
    }
}

// ============ sparse conv via mma.sync bf16-split — 512 threads, warp-tile 32x32 ============
template<bool SELF>
__global__ void __launch_bounds__(512, 1)
conv_mma_kernel(const float* __restrict__ pts,
                const int*   __restrict__ vc,
                float*       __restrict__ out) {
    extern __shared__ char smem[];
    u32* s_bhi = (u32*)(smem + SM_BHI);
    u32* s_blo = (u32*)(smem + SM_BLO);
    __shared__ int s_out[128];
    __shared__ int s_nid[128];
    __shared__ float s_sc[128], s_bi[128];

    int tid = threadIdx.x;
    int wid = tid >> 5;
    int lane = tid & 31;
    int g = lane >> 2, t = lane & 3;
    int warpRow = (wid >> 2) * 32;   // 4 M-groups
    int warpCol = (wid & 3) * 32;    // 4 N-groups

    int k, np, tile0, tstep, tpair;
    if (SELF) { k = 13; np = M_PTS; tile0 = blockIdx.x; tstep = gridDim.x; tpair = 0; }
    else {
        int tt = blockIdx.y;
        k = (tt < 13) ? tt : tt + 1;
        np = g_np[tt];
        tile0 = blockIdx.x; tstep = gridDim.x; tpair = tt;
    }

    // load B hi/lo into smem [n][kin]
    {
        const u32* src_h = (const u32*)(g_wt_hi + (size_t)k*PTS_DIM*KIN);
        const u32* src_l = (const u32*)(g_wt_lo + (size_t)k*PTS_DIM*KIN);
        for (int i = tid; i < 128*112; i += 512) {
            int n = i / 112, kp = i % 112;
            s_bhi[n*B_STRIDE_W + kp] = __ldg(src_h + i);
            s_blo[n*B_STRIDE_W + kp] = __ldg(src_l + i);
        }
        if (SELF && tid < 128) { s_sc[tid] = g_bnscale[tid]; s_bi[tid] = g_bnbias[tid]; }
    }
    __syncthreads();

    for (int tile = tile0; tile*128 < np; tile += tstep) {
        __syncthreads();
        // tile metadata
        if (tid < 128) {
            int r = tile*128 + tid;
            int o = -1, nid = 0;
            if (r < np) {
                if (SELF) {
                    int4 c4 = ((const int4*)vc)[r];
                    o = r;
                    nid = __ldg(&g_grid[(c4.y*GY + c4.z)*GX + c4.w]);
                } else {
                    int2 pr = g_pairs[(size_t)tpair*PAIR_CAP + r];
                    o = pr.x; nid = pr.y;
                }
            }
            s_out[tid] = o;
            s_nid[tid] = nid;
        }
        __syncthreads();

        // my 4 A rows (mi0: g, g+8 ; mi1: g+16, g+24)
        int nidr[4];
        nidr[0] = s_nid[warpRow + g];
        nidr[1] = s_nid[warpRow + g + 8];
        nidr[2] = s_nid[warpRow + g + 16];
        nidr[3] = s_nid[warpRow + g + 24];
        const float* rp[4]; const float* rs[4];
        #pragma unroll
        for (int r = 0; r < 4; r++) {
            rp[r] = pts       + (size_t)nidr[r]*PTS_DIM + 2*t;
            rs[r] = g_sampled + (size_t)nidr[r]*C_IMG  + 2*t;
        }

        float acc[2][4][4];
        #pragma unroll
        for (int mi = 0; mi < 2; mi++)
            #pragma unroll
            for (int ni = 0; ni < 4; ni++)
                #pragma unroll
                for (int j = 0; j < 4; j++) acc[mi][ni][j] = 0.0f;

        // barrier-free mainloop
        #pragma unroll 1
        for (int c = 0; c < NCHUNK; c++) {
            int kb = c * 16;
            u32 fh[4][2], fl[4][2];   // [row][0: k+0..1, 1: k+8..9]
            #pragma unroll
            for (int r = 0; r < 4; r++) {
                const float* base = (kb < PTS_DIM) ? (rp[r] + kb) : (rs[r] + (kb - PTS_DIM));
                float2 v0 = __ldg((const float2*)base);
                float2 v1 = __ldg((const float2*)(base + 8));
                split2(v0.x, v0.y, fh[r][0], fl[r][0]);
                split2(v1.x, v1.y, fh[r][1], fl[r][1]);
            }
            u32 fa_h[2][4] = {{fh[0][0], fh[1][0], fh[0][1], fh[1][1]},
                              {fh[2][0], fh[3][0], fh[2][1], fh[3][1]}};
            u32 fa_l[2][4] = {{fl[0][0], fl[1][0], fl[0][1], fl[1][1]},
                              {fl[2][0], fl[3][0], fl[2][1], fl[3][1]}};

            int koff = c*8 + t;
            #pragma unroll
            for (int ni = 0; ni < 4; ni++) {
                int n = warpCol + ni*8 + g;
                u32 bh0 = s_bhi[n*B_STRIDE_W + koff];
                u32 bh1 = s_bhi[n*B_STRIDE_W + koff + 4];
                u32 bl0 = s_blo[n*B_STRIDE_W + koff];
                u32 bl1 = s_blo[n*B_STRIDE_W + koff + 4];
                #pragma unroll
                for (int mi = 0; mi < 2; mi++) {
                    MMA_BF16(acc[mi][ni], fa_h[mi], bh0, bh1);
                    MMA_BF16(acc[mi][ni], fa_h[mi], bl0, bl1);
                    MMA_BF16(acc[mi][ni], fa_l[mi], bh0, bh1);
                }
            }
        }

        // epilogue from registers
        #pragma unroll
        for (int mi = 0; mi < 2; mi++) {
            int r0 = warpRow + mi*16 + g;
            int o0 = s_out[r0], o1 = s_out[r0 + 8];
            #pragma unroll
            for (int ni = 0; ni < 4; ni++) {
                int n0 = warpCol + ni*8 + t*2;
                if (SELF) {
                    float sc0 = s_sc[n0], sc1 = s_sc[n0+1];
                    float bi0 = s_bi[n0], bi1 = s_bi[n0+1];
                    if (o0 >= 0) {
                        float a0 = g_acc[(size_t)o0*PTS_DIM + n0];
                        float a1 = g_acc[(size_t)o0*PTS_DIM + n0 + 1];
                        out[(size_t)o0*PTS_DIM + n0]     = fmaxf((acc[mi][ni][0]+a0)*sc0+bi0, 0.f);
                        out[(size_t)o0*PTS_DIM + n0 + 1] = fmaxf((acc[mi][ni][1]+a1)*sc1+bi1, 0.f);
                    }
                    if (o1 >= 0) {
                        float a2 = g_acc[(size_t)o1*PTS_DIM + n0];
                        float a3 = g_acc[(size_t)o1*PTS_DIM + n0 + 1];
                        out[(size_t)o1*PTS_DIM + n0]     = fmaxf((acc[mi][ni][2]+a2)*sc0+bi0, 0.f);
                        out[(size_t)o1*PTS_DIM + n0 + 1] = fmaxf((acc[mi][ni][3]+a3)*sc1+bi1, 0.f);
                    }
                } else {
                    if (o0 >= 0) {
                        atomicAdd(&g_acc[(size_t)o0*PTS_DIM + n0],     acc[mi][ni][0]);
                        atomicAdd(&g_acc[(size_t)o0*PTS_DIM + n0 + 1], acc[mi][ni][1]);
                    }
                    if (o1 >= 0) {
                        atomicAdd(&g_acc[(size_t)o1*PTS_DIM + n0],     acc[mi][ni][2]);
                        atomicAdd(&g_acc[(size_t)o1*PTS_DIM + n0 + 1], acc[mi][ni][3]);
                    }
                }
            }
        }
    }
}

// ---------------- launch ----------------
extern "C" void kernel_launch(void* const* d_in, const int* in_sizes, int n_in,
                              void* d_out, int out_size) {
    const float* pts   = (const float*)d_in[0];
    const int*   vc    = (const int*)  d_in[1];
    const float* img   = (const float*)d_in[2];
    const float* l2i   = (const float*)d_in[3];
    const float* iaug  = (const float*)d_in[4];
    const float* laug  = (const float*)d_in[5];
    const float* convw = (const float*)d_in[6];
    const float* gamma = (const float*)d_in[7];
    const float* beta  = (const float*)d_in[8];
    const float* mean  = (const float*)d_in[9];
    const float* var   = (const float*)d_in[10];
    float* out = (float*)d_out;

    cudaFuncSetAttribute(conv_mma_kernel<false>, cudaFuncAttributeMaxDynamicSharedMemorySize, SMEM_CONV);
    cudaFuncSetAttribute(conv_mma_kernel<true>,  cudaFuncAttributeMaxDynamicSharedMemorySize, SMEM_CONV);

    mega_setup_kernel<<<NB_MEGA1, 256>>>(img, convw, l2i, iaug, laug, gamma, beta, mean, var);
    scatter_kernel<<<(M_PTS + 255)/256, 256>>>(vc);
    mega_mid_kernel<<<NB_MEGA2, 256>>>(vc);
    conv_mma_kernel<false><<<dim3(12, NTAP_O), 512, SMEM_CONV>>>(pts, vc, out);
    conv_mma_kernel<true ><<<dim3(148, 1),     512, SMEM_CONV>>>(pts, vc, out);
}